// round 6
// baseline (speedup 1.0000x reference)
#include <cuda_runtime.h>
#include <cuda_bf16.h>
#include <cstdint>
#include <math.h>

#define BDIM 4
#define TDIM 2048
#define CDIM 4096
#define FDIM 14336
#define MDIM (BDIM * TDIM)   // 8192

#define QMAX 126.0f
#define QS   252.0f
#define QSI  (1.0f / 252.0f)

// ---------------- scratch (device globals; allocation-free rule) -----------
__device__ int8_t g_xk1[(size_t)MDIM * CDIM];
__device__ int8_t g_xk2[(size_t)MDIM * CDIM];
__device__ int8_t g_xr1[(size_t)MDIM * CDIM];
__device__ int8_t g_xr2[(size_t)MDIM * CDIM];
__device__ int8_t g_kw1[(size_t)FDIM * CDIM];
__device__ int8_t g_kw2[(size_t)FDIM * CDIM];
__device__ int8_t g_rw1[(size_t)CDIM * CDIM];
__device__ int8_t g_rw2[(size_t)CDIM * CDIM];
__device__ float  g_qak[MDIM];
__device__ float  g_qar[MDIM];
__device__ float  g_qkw[FDIM];
__device__ float  g_qrw[CDIM];
__device__ __nv_bfloat16 g_sh [(size_t)MDIM * FDIM];
__device__ __nv_bfloat16 g_sl [(size_t)MDIM * FDIM];
__device__ __nv_bfloat16 g_vwh[(size_t)CDIM * FDIM];
__device__ __nv_bfloat16 g_vwl[(size_t)CDIM * FDIM];
__device__ float  g_r  [(size_t)MDIM * CDIM];

// ---------------- helpers ----------------------------------------------------
__device__ __forceinline__ uint32_t smem_u32(const void* p) {
    uint32_t a;
    asm("{ .reg .u64 t; cvta.to.shared.u64 t, %1; cvt.u32.u64 %0, t; }" : "=r"(a) : "l"(p));
    return a;
}
__device__ __forceinline__ void cpa16(uint32_t dst, const void* src) {
    asm volatile("cp.async.cg.shared.global [%0], [%1], 16;" :: "r"(dst), "l"(src));
}
__device__ __forceinline__ void ldsm4(uint32_t& r0, uint32_t& r1, uint32_t& r2, uint32_t& r3,
                                      uint32_t addr) {
    asm volatile("ldmatrix.sync.aligned.m8n8.x4.shared.b16 {%0,%1,%2,%3}, [%4];"
                 : "=r"(r0), "=r"(r1), "=r"(r2), "=r"(r3) : "r"(addr));
}
__device__ __forceinline__ void mma_bf16(float* c, const uint32_t* a, const uint32_t* b) {
    asm volatile(
        "mma.sync.aligned.m16n8k16.row.col.f32.bf16.bf16.f32 "
        "{%0,%1,%2,%3}, {%4,%5,%6,%7}, {%8,%9}, {%0,%1,%2,%3};"
        : "+f"(c[0]), "+f"(c[1]), "+f"(c[2]), "+f"(c[3])
        : "r"(a[0]), "r"(a[1]), "r"(a[2]), "r"(a[3]), "r"(b[0]), "r"(b[1]));
}
__device__ __forceinline__ void mma_s8(int* c, const uint32_t* a, const uint32_t* b) {
    asm volatile(
        "mma.sync.aligned.m16n8k32.row.col.s32.s8.s8.s32 "
        "{%0,%1,%2,%3}, {%4,%5,%6,%7}, {%8,%9}, {%0,%1,%2,%3};"
        : "+r"(c[0]), "+r"(c[1]), "+r"(c[2]), "+r"(c[3])
        : "r"(a[0]), "r"(a[1]), "r"(a[2]), "r"(a[3]), "r"(b[0]), "r"(b[1]));
}
__device__ __forceinline__ uint32_t pbf2(__nv_bfloat16 a, __nv_bfloat16 b) {
    __nv_bfloat162 t = __halves2bfloat162(a, b);
    return *reinterpret_cast<uint32_t*>(&t);
}
__device__ __forceinline__ void split1(float v, __nv_bfloat16& h, __nv_bfloat16& l) {
    h = __float2bfloat16_rn(v);
    l = __float2bfloat16_rn(v - __bfloat162float(h));
}
__device__ __forceinline__ uint32_t pk4b(int a, int b, int c, int d) {
    return (uint32_t)(uint8_t)a | ((uint32_t)(uint8_t)b << 8) |
           ((uint32_t)(uint8_t)c << 16) | ((uint32_t)(uint8_t)d << 24);
}

// block-wide max over 256 threads, result broadcast to all
__device__ __forceinline__ float blockmax256(float v, float* sh8, int tid) {
#pragma unroll
    for (int o = 16; o > 0; o >>= 1)
        v = fmaxf(v, __shfl_xor_sync(0xFFFFFFFFu, v, o));
    if ((tid & 31) == 0) sh8[tid >> 5] = v;
    __syncthreads();
    float m = fmaxf(fmaxf(fmaxf(sh8[0], sh8[1]), fmaxf(sh8[2], sh8[3])),
                    fmaxf(fmaxf(sh8[4], sh8[5]), fmaxf(sh8[6], sh8[7])));
    return m;
}

// quantize 16 values -> two uint4 digit words
__device__ __forceinline__ void q16(const float* v, float s, uint4& w1, uint4& w2) {
    int d1[16], d2[16];
#pragma unroll
    for (int j = 0; j < 16; ++j) {
        float t = v[j] * s;
        d1[j] = __float2int_rn(t);
        d2[j] = __float2int_rn((t - (float)d1[j]) * QS);
    }
    w1 = make_uint4(pk4b(d1[0], d1[1], d1[2], d1[3]),   pk4b(d1[4], d1[5], d1[6], d1[7]),
                    pk4b(d1[8], d1[9], d1[10], d1[11]), pk4b(d1[12], d1[13], d1[14], d1[15]));
    w2 = make_uint4(pk4b(d2[0], d2[1], d2[2], d2[3]),   pk4b(d2[4], d2[5], d2[6], d2[7]),
                    pk4b(d2[8], d2[9], d2[10], d2[11]), pk4b(d2[12], d2[13], d2[14], d2[15]));
}

// ---------------- elementwise / quant kernels --------------------------------
// one block per row: token-shift mix then per-row int8 2-digit quantization
__global__ void __launch_bounds__(256)
mix_quant_kernel(const float4* __restrict__ x, const float4* __restrict__ ls,
                 const float4* __restrict__ mk, const float4* __restrict__ mr,
                 uint4* __restrict__ xk1, uint4* __restrict__ xk2,
                 uint4* __restrict__ xr1, uint4* __restrict__ xr2,
                 float* __restrict__ qak, float* __restrict__ qar) {
    __shared__ float sh8a[8], sh8b[8];
    const int row = blockIdx.x;
    const int tid = threadIdx.x;
    const int t = row % TDIM, b = row / TDIM;
    const int C4 = CDIM / 4;
    const size_t base4 = (size_t)row * C4;

    float xk[16], xr[16];
    float mka = 0.0f, mra = 0.0f;
#pragma unroll
    for (int i = 0; i < 4; ++i) {
        int c4 = tid * 4 + i;
        float4 xv = x[base4 + c4];
        float4 pv = (t == 0) ? ls[(size_t)b * C4 + c4] : x[base4 - C4 + c4];
        float4 k4 = mk[c4];
        float4 r4 = mr[c4];
        float* K = xk + i * 4;
        float* R = xr + i * 4;
        K[0] = fmaf(pv.x - xv.x, k4.x, xv.x);
        K[1] = fmaf(pv.y - xv.y, k4.y, xv.y);
        K[2] = fmaf(pv.z - xv.z, k4.z, xv.z);
        K[3] = fmaf(pv.w - xv.w, k4.w, xv.w);
        R[0] = fmaf(pv.x - xv.x, r4.x, xv.x);
        R[1] = fmaf(pv.y - xv.y, r4.y, xv.y);
        R[2] = fmaf(pv.z - xv.z, r4.z, xv.z);
        R[3] = fmaf(pv.w - xv.w, r4.w, xv.w);
#pragma unroll
        for (int j = 0; j < 4; ++j) {
            mka = fmaxf(mka, fabsf(K[j]));
            mra = fmaxf(mra, fabsf(R[j]));
        }
    }
    float Mk = blockmax256(mka, sh8a, tid);
    float Mr = blockmax256(mra, sh8b, tid);
    float sk = (Mk > 0.0f) ? QMAX / Mk : 0.0f;
    float sr = (Mr > 0.0f) ? QMAX / Mr : 0.0f;
    if (tid == 0) { qak[row] = Mk / QMAX; qar[row] = Mr / QMAX; }

    const size_t o = (size_t)row * 256 + tid;   // uint4 index (16 bytes each)
    uint4 w1, w2;
    q16(xk, sk, w1, w2);
    xk1[o] = w1; xk2[o] = w2;
    q16(xr, sr, w1, w2);
    xr1[o] = w1; xr2[o] = w2;
}

// one block per weight row (K=4096)
__global__ void __launch_bounds__(256)
quant_w_kernel(const float4* __restrict__ w,
               uint4* __restrict__ w1p, uint4* __restrict__ w2p,
               float* __restrict__ q) {
    __shared__ float sh8[8];
    const int row = blockIdx.x;
    const int tid = threadIdx.x;
    const size_t base4 = (size_t)row * (CDIM / 4);

    float v[16];
    float ma = 0.0f;
#pragma unroll
    for (int i = 0; i < 4; ++i) {
        float4 a = w[base4 + tid * 4 + i];
        v[i * 4 + 0] = a.x; v[i * 4 + 1] = a.y;
        v[i * 4 + 2] = a.z; v[i * 4 + 3] = a.w;
        ma = fmaxf(ma, fmaxf(fmaxf(fabsf(a.x), fabsf(a.y)), fmaxf(fabsf(a.z), fabsf(a.w))));
    }
    float M = blockmax256(ma, sh8, tid);
    float s = (M > 0.0f) ? QMAX / M : 0.0f;
    if (tid == 0) q[row] = M / QMAX;

    uint4 w1, w2;
    q16(v, s, w1, w2);
    const size_t o = (size_t)row * 256 + tid;
    w1p[o] = w1; w2p[o] = w2;
}

__global__ void split_kernel(const float4* __restrict__ in,
                             uint4* __restrict__ oh, uint4* __restrict__ ol,
                             size_t n8) {
    size_t i = (size_t)blockIdx.x * blockDim.x + threadIdx.x;
    if (i >= n8) return;
    float4 a = in[2 * i], b = in[2 * i + 1];
    float v[8] = {a.x, a.y, a.z, a.w, b.x, b.y, b.z, b.w};
    uint32_t hw[4], lw[4];
#pragma unroll
    for (int j = 0; j < 4; ++j) {
        __nv_bfloat16 h0, l0, h1, l1;
        split1(v[2 * j], h0, l0);
        split1(v[2 * j + 1], h1, l1);
        hw[j] = pbf2(h0, h1);
        lw[j] = pbf2(l0, l1);
    }
    oh[i] = make_uint4(hw[0], hw[1], hw[2], hw[3]);
    ol[i] = make_uint4(lw[0], lw[1], lw[2], lw[3]);
}

__global__ void state_kernel(const float* __restrict__ x, float* __restrict__ outs) {
    int idx = blockIdx.x * blockDim.x + threadIdx.x;
    int b = idx / CDIM;
    int c = idx % CDIM;
    outs[idx] = x[((size_t)b * TDIM + (TDIM - 1)) * CDIM + c];
}

// ---------------- int8 IMMA GEMM ----------------------------------------------
// C[M,N] = dequant( A(2-digit s8)[M,K] * B(2-digit s8)[N,K]^T )
// CTA 128x128, 16 warps (warp 32x32), BK=64 bytes, 3-stage cp.async.
// stage: A1(128x80) | A2 | B1 | B2
#define IROWB  80
#define ISEC   (128 * IROWB)          // 10240
#define ISTAGE (4 * ISEC)             // 40960
#define INST   3
#define ISMEM  (INST * ISTAGE)        // 122880

__global__ void __launch_bounds__(512, 1)
gemm_imma(const int8_t* __restrict__ A1, const int8_t* __restrict__ A2,
          const int8_t* __restrict__ B1, const int8_t* __restrict__ B2,
          const float* __restrict__ qa, const float* __restrict__ qb,
          int N, int K, int Ntiles, int epi,
          float* __restrict__ Cf,
          __nv_bfloat16* __restrict__ Ch, __nv_bfloat16* __restrict__ Cl) {
    extern __shared__ char smem[];
    const uint32_t sb = smem_u32(smem);
    const int tid  = threadIdx.x;
    const int wid  = tid >> 5;
    const int lane = tid & 31;
    const int wm   = wid & 3;        // 4 warp-rows (32 each)
    const int wn   = wid >> 2;       // 4 warp-cols (32 each)

    int bid = blockIdx.x;
    int bandCtas = 16 * Ntiles;
    int band = bid / bandCtas, rmd = bid % bandCtas;
    int nt = rmd >> 4;
    int mt = band * 16 + (rmd & 15);
    const size_t m0 = (size_t)mt * 128;
    const size_t n0 = (size_t)nt * 128;

    const char* pA1 = (const char*)(A1 + m0 * (size_t)K);
    const char* pA2 = (const char*)(A2 + m0 * (size_t)K);
    const char* pB1 = (const char*)(B1 + n0 * (size_t)K);
    const char* pB2 = (const char*)(B2 + n0 * (size_t)K);

    const int nk = K >> 6;   // BK = 64 bytes

    const int cr = tid >> 2;   // row 0..127
    const int cc = tid & 3;    // 16B chunk

    // prologue: stages 0, 1
#pragma unroll
    for (int s = 0; s < 2; ++s) {
        const uint32_t base = sb + s * ISTAGE;
        const size_t kb = (size_t)s * 64;
        uint32_t off = (uint32_t)(cr * IROWB + cc * 16);
        size_t g = (size_t)cr * K + kb + (size_t)cc * 16;
        cpa16(base + off,            pA1 + g);
        cpa16(base + ISEC + off,     pA2 + g);
        cpa16(base + 2 * ISEC + off, pB1 + g);
        cpa16(base + 3 * ISEC + off, pB2 + g);
        asm volatile("cp.async.commit_group;" ::: "memory");
    }

    int accM[2][4][4], accX[2][4][4];
#pragma unroll
    for (int i = 0; i < 2; ++i)
#pragma unroll
        for (int j = 0; j < 4; ++j)
#pragma unroll
            for (int q = 0; q < 4; ++q) { accM[i][j][q] = 0; accX[i][j][q] = 0; }

    const uint32_t a_lo = (uint32_t)(((lane & 7) + ((lane >> 3) & 1) * 8) * IROWB + (lane >> 4) * 16);
    const uint32_t b_lo = (uint32_t)(((lane & 7) + (lane >> 4) * 8) * IROWB + ((lane >> 3) & 1) * 16);

    for (int kt = 0; kt < nk; ++kt) {
        asm volatile("cp.async.wait_group 1;" ::: "memory");
        __syncthreads();

        const uint32_t sbase = sb + (kt % INST) * ISTAGE;
        const uint32_t a1s = sbase;
        const uint32_t a2s = sbase + ISEC;
        const uint32_t b1s = sbase + 2 * ISEC;
        const uint32_t b2s = sbase + 3 * ISEC;

#pragma unroll
        for (int kk = 0; kk < 2; ++kk) {
            const uint32_t kbyte = kk * 32;
            uint32_t a1[2][4], a2[2][4], b1[4][2], b2[4][2];
#pragma unroll
            for (int mi = 0; mi < 2; ++mi) {
                uint32_t ra = (uint32_t)((wm * 32 + mi * 16) * IROWB) + kbyte + a_lo;
                ldsm4(a1[mi][0], a1[mi][1], a1[mi][2], a1[mi][3], a1s + ra);
                ldsm4(a2[mi][0], a2[mi][1], a2[mi][2], a2[mi][3], a2s + ra);
            }
#pragma unroll
            for (int p = 0; p < 2; ++p) {
                uint32_t rb = (uint32_t)((wn * 32 + p * 16) * IROWB) + kbyte + b_lo;
                uint32_t t0, t1, t2, t3;
                ldsm4(t0, t1, t2, t3, b1s + rb);
                b1[p * 2][0] = t0; b1[p * 2][1] = t1;
                b1[p * 2 + 1][0] = t2; b1[p * 2 + 1][1] = t3;
                ldsm4(t0, t1, t2, t3, b2s + rb);
                b2[p * 2][0] = t0; b2[p * 2][1] = t1;
                b2[p * 2 + 1][0] = t2; b2[p * 2 + 1][1] = t3;
            }
#pragma unroll
            for (int mi = 0; mi < 2; ++mi)
#pragma unroll
                for (int nj = 0; nj < 4; ++nj) {
                    mma_s8(accM[mi][nj], a1[mi], b1[nj]);
                    mma_s8(accX[mi][nj], a1[mi], b2[nj]);
                    mma_s8(accX[mi][nj], a2[mi], b1[nj]);
                }
        }

        if (kt + 2 < nk) {
            const uint32_t base = sb + ((kt + 2) % INST) * ISTAGE;
            const size_t kb = (size_t)(kt + 2) * 64;
            uint32_t off = (uint32_t)(cr * IROWB + cc * 16);
            size_t g = (size_t)cr * K + kb + (size_t)cc * 16;
            cpa16(base + off,            pA1 + g);
            cpa16(base + ISEC + off,     pA2 + g);
            cpa16(base + 2 * ISEC + off, pB1 + g);
            cpa16(base + 3 * ISEC + off, pB2 + g);
        }
        asm volatile("cp.async.commit_group;" ::: "memory");
    }

    // ---- epilogue: dequant + activation ----
    const size_t mw = m0 + wm * 32;
    const size_t nw = n0 + wn * 32;
    const int tr = lane >> 2;
    const int tc = (lane & 3) * 2;

#pragma unroll
    for (int mi = 0; mi < 2; ++mi) {
#pragma unroll
        for (int nj = 0; nj < 4; ++nj) {
            const int* cm = accM[mi][nj];
            const int* cx = accX[mi][nj];
            const size_t row = mw + mi * 16 + tr;
            const size_t col = nw + nj * 8 + tc;
            const float qb0 = qb[col], qb1 = qb[col + 1];
#pragma unroll
            for (int h = 0; h < 2; ++h) {
                const size_t rr = row + h * 8;
                const size_t base = rr * (size_t)N + col;
                const float qav = qa[rr];
                float v0 = ((float)cm[h * 2]     + (float)cx[h * 2]     * QSI) * qav * qb0;
                float v1 = ((float)cm[h * 2 + 1] + (float)cx[h * 2 + 1] * QSI) * qav * qb1;
                if (epi == 0) {                 // relu^2 -> bf16 split
                    v0 = fmaxf(v0, 0.0f); v0 *= v0;
                    v1 = fmaxf(v1, 0.0f); v1 *= v1;
                    __nv_bfloat16 h0, l0, h1, l1;
                    split1(v0, h0, l0);
                    split1(v1, h1, l1);
                    *reinterpret_cast<uint32_t*>(Ch + base) = pbf2(h0, h1);
                    *reinterpret_cast<uint32_t*>(Cl + base) = pbf2(l0, l1);
                } else {                        // sigmoid -> fp32
                    float2 o;
                    o.x = 1.0f / (1.0f + expf(-v0));
                    o.y = 1.0f / (1.0f + expf(-v1));
                    *reinterpret_cast<float2*>(Cf + base) = o;
                }
            }
        }
    }
}

// ---------------- bf16 HMMA GEMM (GEMM3) ---------------------------------------
// CTA 128x256, 16 warps, warp 64x32, BK=32, 3-stage. epi: v * Rm
#define ROWB   80
#define ASEC   (128 * ROWB)
#define BSEC   (256 * ROWB)
#define STAGEB (2 * ASEC + 2 * BSEC)
#define NSTAGE 3
#define SMEMSZ (NSTAGE * STAGEB)

__global__ void __launch_bounds__(512, 1)
gemm_mma(const __nv_bfloat16* __restrict__ Ah, const __nv_bfloat16* __restrict__ Al,
         const __nv_bfloat16* __restrict__ Bh, const __nv_bfloat16* __restrict__ Bl,
         int N, int K, int Ntiles,
         float* __restrict__ Cf, const float* __restrict__ Rm) {
    extern __shared__ char smem[];
    const uint32_t sb = smem_u32(smem);
    const int tid  = threadIdx.x;
    const int wid  = tid >> 5;
    const int lane = tid & 31;
    const int wm   = wid & 1;
    const int wn   = wid >> 1;

    int bid = blockIdx.x;
    int bandCtas = 16 * Ntiles;
    int band = bid / bandCtas, rmd = bid % bandCtas;
    int nt = rmd >> 4;
    int mt = band * 16 + (rmd & 15);
    const size_t m0 = (size_t)mt * 128;
    const size_t n0 = (size_t)nt * 256;

    const size_t K2 = (size_t)K * 2;
    const char* pAh = (const char*)(Ah + m0 * (size_t)K);
    const char* pAl = (const char*)(Al + m0 * (size_t)K);
    const char* pBh = (const char*)(Bh + n0 * (size_t)K);
    const char* pBl = (const char*)(Bl + n0 * (size_t)K);

    const int nk = K >> 5;

    const int cr = tid >> 2;
    const int cc = tid & 3;

#pragma unroll
    for (int s = 0; s < 2; ++s) {
        const uint32_t base = sb + s * STAGEB;
        const size_t kb = (size_t)s * 64;
        {
            uint32_t off = (uint32_t)(cr * ROWB + cc * 16);
            size_t g = (size_t)cr * K2 + kb + (size_t)cc * 16;
            cpa16(base + off,        pAh + g);
            cpa16(base + ASEC + off, pAl + g);
        }
#pragma unroll
        for (int it = 0; it < 2; ++it) {
            int r = cr + it * 128;
            uint32_t off = (uint32_t)(r * ROWB + cc * 16);
            size_t g = (size_t)r * K2 + kb + (size_t)cc * 16;
            cpa16(base + 2 * ASEC + off,        pBh + g);
            cpa16(base + 2 * ASEC + BSEC + off, pBl + g);
        }
        asm volatile("cp.async.commit_group;" ::: "memory");
    }

    float acc[4][4][4];
#pragma unroll
    for (int i = 0; i < 4; ++i)
#pragma unroll
        for (int j = 0; j < 4; ++j)
#pragma unroll
            for (int q = 0; q < 4; ++q) acc[i][j][q] = 0.0f;

    const uint32_t a_lo = (uint32_t)(((lane & 7) + ((lane >> 3) & 1) * 8) * ROWB + (lane >> 4) * 16);
    const uint32_t b_lo = (uint32_t)(((lane & 7) + (lane >> 4) * 8) * ROWB + ((lane >> 3) & 1) * 16);

    for (int kt = 0; kt < nk; ++kt) {
        asm volatile("cp.async.wait_group 1;" ::: "memory");
        __syncthreads();

        const uint32_t sbase = sb + (kt % NSTAGE) * STAGEB;
        const uint32_t aH = sbase;
        const uint32_t aL = sbase + ASEC;
        const uint32_t bH = sbase + 2 * ASEC;
        const uint32_t bL = sbase + 2 * ASEC + BSEC;

#pragma unroll
        for (int kk = 0; kk < 2; ++kk) {
            const uint32_t kbyte = kk * 32;
            uint32_t ah[4][4], al[4][4], bh[4][2], bl[4][2];
#pragma unroll
            for (int mi = 0; mi < 4; ++mi) {
                uint32_t ra = (uint32_t)((wm * 64 + mi * 16) * ROWB) + kbyte + a_lo;
                ldsm4(ah[mi][0], ah[mi][1], ah[mi][2], ah[mi][3], aH + ra);
                ldsm4(al[mi][0], al[mi][1], al[mi][2], al[mi][3], aL + ra);
            }
#pragma unroll
            for (int nj = 0; nj < 2; ++nj) {
                uint32_t rb = (uint32_t)((wn * 32 + nj * 16) * ROWB) + kbyte + b_lo;
                uint32_t t0, t1, t2, t3;
                ldsm4(t0, t1, t2, t3, bH + rb);
                bh[nj * 2][0] = t0; bh[nj * 2][1] = t1;
                bh[nj * 2 + 1][0] = t2; bh[nj * 2 + 1][1] = t3;
                ldsm4(t0, t1, t2, t3, bL + rb);
                bl[nj * 2][0] = t0; bl[nj * 2][1] = t1;
                bl[nj * 2 + 1][0] = t2; bl[nj * 2 + 1][1] = t3;
            }
#pragma unroll
            for (int mi = 0; mi < 4; ++mi)
#pragma unroll
                for (int ni = 0; ni < 4; ++ni) {
                    float* c = acc[mi][ni];
                    mma_bf16(c, ah[mi], bh[ni]);
                    mma_bf16(c, ah[mi], bl[ni]);
                    mma_bf16(c, al[mi], bh[ni]);
                }
        }

        if (kt + 2 < nk) {
            const uint32_t base = sb + ((kt + 2) % NSTAGE) * STAGEB;
            const size_t kb = (size_t)(kt + 2) * 64;
            {
                uint32_t off = (uint32_t)(cr * ROWB + cc * 16);
                size_t g = (size_t)cr * K2 + kb + (size_t)cc * 16;
                cpa16(base + off,        pAh + g);
                cpa16(base + ASEC + off, pAl + g);
            }
#pragma unroll
            for (int it = 0; it < 2; ++it) {
                int r = cr + it * 128;
                uint32_t off = (uint32_t)(r * ROWB + cc * 16);
                size_t g = (size_t)r * K2 + kb + (size_t)cc * 16;
                cpa16(base + 2 * ASEC + off,        pBh + g);
                cpa16(base + 2 * ASEC + BSEC + off, pBl + g);
            }
        }
        asm volatile("cp.async.commit_group;" ::: "memory");
    }

    const size_t mw = m0 + wm * 64;
    const size_t nw = n0 + wn * 32;
    const int tr = lane >> 2;
    const int tc = (lane & 3) * 2;

#pragma unroll
    for (int mi = 0; mi < 4; ++mi) {
#pragma unroll
        for (int nj = 0; nj < 4; ++nj) {
            const float* c = acc[mi][nj];
            const size_t row = mw + mi * 16 + tr;
            const size_t col = nw + nj * 8 + tc;
#pragma unroll
            for (int h = 0; h < 2; ++h) {
                const size_t rr = row + h * 8;
                const size_t base = rr * (size_t)N + col;
                float2 rv = *reinterpret_cast<const float2*>(Rm + base);
                float2 o;
                o.x = c[h * 2] * rv.x;
                o.y = c[h * 2 + 1] * rv.y;
                *reinterpret_cast<float2*>(Cf + base) = o;
            }
        }
    }
}

// ---------------- launch -----------------------------------------------------
extern "C" void kernel_launch(void* const* d_in, const int* in_sizes, int n_in,
                              void* d_out, int out_size) {
    const float* x  = (const float*)d_in[0];
    const float* ls = (const float*)d_in[1];
    const float* mk = (const float*)d_in[2];
    const float* mr = (const float*)d_in[3];
    const float* kw = (const float*)d_in[4];   // (F, C)
    const float* rw = (const float*)d_in[5];   // (C, C)
    const float* vw = (const float*)d_in[6];   // (C, F)
    float* out = (float*)d_out;

    int8_t *xk1, *xk2, *xr1, *xr2, *kw1, *kw2, *rw1, *rw2;
    float *qak, *qar, *qkw, *qrw, *r;
    __nv_bfloat16 *sh, *sl, *vwh, *vwl;
    cudaGetSymbolAddress((void**)&xk1, g_xk1);
    cudaGetSymbolAddress((void**)&xk2, g_xk2);
    cudaGetSymbolAddress((void**)&xr1, g_xr1);
    cudaGetSymbolAddress((void**)&xr2, g_xr2);
    cudaGetSymbolAddress((void**)&kw1, g_kw1);
    cudaGetSymbolAddress((void**)&kw2, g_kw2);
    cudaGetSymbolAddress((void**)&rw1, g_rw1);
    cudaGetSymbolAddress((void**)&rw2, g_rw2);
    cudaGetSymbolAddress((void**)&qak, g_qak);
    cudaGetSymbolAddress((void**)&qar, g_qar);
    cudaGetSymbolAddress((void**)&qkw, g_qkw);
    cudaGetSymbolAddress((void**)&qrw, g_qrw);
    cudaGetSymbolAddress((void**)&sh,  g_sh);
    cudaGetSymbolAddress((void**)&sl,  g_sl);
    cudaGetSymbolAddress((void**)&vwh, g_vwh);
    cudaGetSymbolAddress((void**)&vwl, g_vwl);
    cudaGetSymbolAddress((void**)&r,   g_r);

    cudaFuncSetAttribute(gemm_imma, cudaFuncAttributeMaxDynamicSharedMemorySize, ISMEM);
    cudaFuncSetAttribute(gemm_mma,  cudaFuncAttributeMaxDynamicSharedMemorySize, SMEMSZ);

    // 1) mix + int8 quant of xk, xr
    mix_quant_kernel<<<MDIM, 256>>>((const float4*)x, (const float4*)ls,
                                    (const float4*)mk, (const float4*)mr,
                                    (uint4*)xk1, (uint4*)xk2, (uint4*)xr1, (uint4*)xr2,
                                    qak, qar);

    // 2) weight quant (int8) + vw split (bf16)
    quant_w_kernel<<<FDIM, 256>>>((const float4*)kw, (uint4*)kw1, (uint4*)kw2, qkw);
    quant_w_kernel<<<CDIM, 256>>>((const float4*)rw, (uint4*)rw1, (uint4*)rw2, qrw);
    {
        size_t n8 = (size_t)CDIM * FDIM / 8;
        split_kernel<<<(unsigned)((n8 + 255) / 256), 256>>>((const float4*)vw, (uint4*)vwh, (uint4*)vwl, n8);
    }

    // 3) S = relu(xk @ Kw^T)^2 -> bf16 split      [8192 x 14336, K=4096] int8
    gemm_imma<<<(MDIM / 128) * (FDIM / 128), 512, ISMEM>>>(
        xk1, xk2, kw1, kw2, qak, qkw, FDIM, CDIM, FDIM / 128, 0, nullptr, sh, sl);

    // 4) R = sigmoid(xr @ Rw^T) -> fp32           [8192 x 4096, K=4096] int8
    gemm_imma<<<(MDIM / 128) * (CDIM / 128), 512, ISMEM>>>(
        xr1, xr2, rw1, rw2, qar, qrw, CDIM, CDIM, CDIM / 128, 1, r, nullptr, nullptr);

    // 5) out = R * (S @ Vw^T)   -> fp32           [8192 x 4096, K=14336] bf16
    gemm_mma<<<(MDIM / 128) * (CDIM / 256), 512, SMEMSZ>>>(
        sh, sl, vwh, vwl, CDIM, FDIM, CDIM / 256, out, r);

    // 6) new_state = x[:, -1, :]
    state_kernel<<<(BDIM * CDIM) / 256, 256>>>(x, out + (size_t)MDIM * CDIM);
}

// round 7
// speedup vs baseline: 2.2591x; 2.2591x over previous
#include <cuda_runtime.h>
#include <cuda_bf16.h>
#include <cstdint>
#include <math.h>

#define BDIM 4
#define TDIM 2048
#define CDIM 4096
#define FDIM 14336
#define MDIM (BDIM * TDIM)   // 8192

// ---------------- scratch (device globals; allocation-free rule) -----------
__device__ __nv_bfloat16 g_xkh[(size_t)MDIM * CDIM];
__device__ __nv_bfloat16 g_xkl[(size_t)MDIM * CDIM];
__device__ __nv_bfloat16 g_xrh[(size_t)MDIM * CDIM];
__device__ __nv_bfloat16 g_xrl[(size_t)MDIM * CDIM];
__device__ __nv_bfloat16 g_sh [(size_t)MDIM * FDIM];
__device__ __nv_bfloat16 g_sl [(size_t)MDIM * FDIM];
__device__ __nv_bfloat16 g_kwh[(size_t)FDIM * CDIM];
__device__ __nv_bfloat16 g_kwl[(size_t)FDIM * CDIM];
__device__ __nv_bfloat16 g_rwh[(size_t)CDIM * CDIM];
__device__ __nv_bfloat16 g_rwl[(size_t)CDIM * CDIM];
__device__ __nv_bfloat16 g_vwh[(size_t)CDIM * FDIM];
__device__ __nv_bfloat16 g_vwl[(size_t)CDIM * FDIM];
__device__ float         g_r  [(size_t)MDIM * CDIM];

// ---------------- helpers ----------------------------------------------------
__device__ __forceinline__ uint32_t smem_u32(const void* p) {
    uint32_t a;
    asm("{ .reg .u64 t; cvta.to.shared.u64 t, %1; cvt.u32.u64 %0, t; }" : "=r"(a) : "l"(p));
    return a;
}
__device__ __forceinline__ void cpa16(uint32_t dst, const void* src) {
    asm volatile("cp.async.cg.shared.global [%0], [%1], 16;" :: "r"(dst), "l"(src));
}
__device__ __forceinline__ void ldsm4(uint32_t& r0, uint32_t& r1, uint32_t& r2, uint32_t& r3,
                                      uint32_t addr) {
    asm volatile("ldmatrix.sync.aligned.m8n8.x4.shared.b16 {%0,%1,%2,%3}, [%4];"
                 : "=r"(r0), "=r"(r1), "=r"(r2), "=r"(r3) : "r"(addr));
}
__device__ __forceinline__ void mma_bf16(float* c, const uint32_t* a, const uint32_t* b) {
    asm volatile(
        "mma.sync.aligned.m16n8k16.row.col.f32.bf16.bf16.f32 "
        "{%0,%1,%2,%3}, {%4,%5,%6,%7}, {%8,%9}, {%0,%1,%2,%3};"
        : "+f"(c[0]), "+f"(c[1]), "+f"(c[2]), "+f"(c[3])
        : "r"(a[0]), "r"(a[1]), "r"(a[2]), "r"(a[3]), "r"(b[0]), "r"(b[1]));
}
__device__ __forceinline__ uint32_t pbf2(__nv_bfloat16 a, __nv_bfloat16 b) {
    __nv_bfloat162 t = __halves2bfloat162(a, b);
    return *reinterpret_cast<uint32_t*>(&t);
}
__device__ __forceinline__ void split1(float v, __nv_bfloat16& h, __nv_bfloat16& l) {
    h = __float2bfloat16_rn(v);
    l = __float2bfloat16_rn(v - __bfloat162float(h));
}

// 64B-row XOR swizzle: 16B chunk index c at row r stored at chunk (c ^ ((r>>1)&3))
__device__ __forceinline__ uint32_t swoff(int r, int c) {
    return (uint32_t)(r * 64 + ((c ^ ((r >> 1) & 3)) << 4));
}

// ---------------- elementwise kernels ---------------------------------------
__global__ void mix_split_kernel(const float4* __restrict__ x,
                                 const float4* __restrict__ ls,
                                 const float4* __restrict__ mk,
                                 const float4* __restrict__ mr,
                                 uint2* __restrict__ xkh, uint2* __restrict__ xkl,
                                 uint2* __restrict__ xrh, uint2* __restrict__ xrl) {
    const int C4 = CDIM / 4;
    int idx = blockIdx.x * blockDim.x + threadIdx.x;
    int c4 = idx % C4;
    int bt = idx / C4;
    int t  = bt % TDIM;
    int b  = bt / TDIM;

    float4 xv = x[idx];
    float4 pv = (t == 0) ? ls[b * C4 + c4] : x[idx - C4];
    float4 k4 = mk[c4];
    float4 r4 = mr[c4];

    float kk[4], rr[4];
    kk[0] = fmaf(pv.x - xv.x, k4.x, xv.x);
    kk[1] = fmaf(pv.y - xv.y, k4.y, xv.y);
    kk[2] = fmaf(pv.z - xv.z, k4.z, xv.z);
    kk[3] = fmaf(pv.w - xv.w, k4.w, xv.w);
    rr[0] = fmaf(pv.x - xv.x, r4.x, xv.x);
    rr[1] = fmaf(pv.y - xv.y, r4.y, xv.y);
    rr[2] = fmaf(pv.z - xv.z, r4.z, xv.z);
    rr[3] = fmaf(pv.w - xv.w, r4.w, xv.w);

    __nv_bfloat16 h0, l0, h1, l1, h2, l2, h3, l3;
    split1(kk[0], h0, l0); split1(kk[1], h1, l1);
    split1(kk[2], h2, l2); split1(kk[3], h3, l3);
    xkh[idx] = make_uint2(pbf2(h0, h1), pbf2(h2, h3));
    xkl[idx] = make_uint2(pbf2(l0, l1), pbf2(l2, l3));
    split1(rr[0], h0, l0); split1(rr[1], h1, l1);
    split1(rr[2], h2, l2); split1(rr[3], h3, l3);
    xrh[idx] = make_uint2(pbf2(h0, h1), pbf2(h2, h3));
    xrl[idx] = make_uint2(pbf2(l0, l1), pbf2(l2, l3));
}

__global__ void split_kernel(const float4* __restrict__ in,
                             uint4* __restrict__ oh, uint4* __restrict__ ol,
                             size_t n8) {
    size_t i = (size_t)blockIdx.x * blockDim.x + threadIdx.x;
    if (i >= n8) return;
    float4 a = in[2 * i], b = in[2 * i + 1];
    float v[8] = {a.x, a.y, a.z, a.w, b.x, b.y, b.z, b.w};
    uint32_t hw[4], lw[4];
#pragma unroll
    for (int j = 0; j < 4; ++j) {
        __nv_bfloat16 h0, l0, h1, l1;
        split1(v[2 * j], h0, l0);
        split1(v[2 * j + 1], h1, l1);
        hw[j] = pbf2(h0, h1);
        lw[j] = pbf2(l0, l1);
    }
    oh[i] = make_uint4(hw[0], hw[1], hw[2], hw[3]);
    ol[i] = make_uint4(lw[0], lw[1], lw[2], lw[3]);
}

__global__ void state_kernel(const float* __restrict__ x, float* __restrict__ outs) {
    int idx = blockIdx.x * blockDim.x + threadIdx.x;
    int b = idx / CDIM;
    int c = idx % CDIM;
    outs[idx] = x[((size_t)b * TDIM + (TDIM - 1)) * CDIM + c];
}

// ---------------- HMMA GEMM --------------------------------------------------
// C[M,N] = A[M,K]*B[N,K]^T, split bf16 3-term, mma.sync m16n8k16 bf16.
// CTA 128x256, 16 warps (512 thr), warp 64x32, BK=32, 4-stage cp.async,
// XOR-swizzled 64B rows (no padding).
// stage: Ah(128x64B) | Al | Bh(256x64B) | Bl
#define ASEC   (128 * 64)            // 8192
#define BSEC   (256 * 64)            // 16384
#define STAGEB (2 * ASEC + 2 * BSEC) // 49152
#define NSTAGE 4
#define SMEMSZ (NSTAGE * STAGEB)     // 196608

__global__ void __launch_bounds__(512, 1)
gemm_mma(const __nv_bfloat16* __restrict__ Ah, const __nv_bfloat16* __restrict__ Al,
         const __nv_bfloat16* __restrict__ Bh, const __nv_bfloat16* __restrict__ Bl,
         int N, int K, int Ntiles, int epi,
         float* __restrict__ Cf,
         __nv_bfloat16* __restrict__ Ch, __nv_bfloat16* __restrict__ Cl,
         const float* __restrict__ Rm) {
    extern __shared__ char smem[];
    const uint32_t sb = smem_u32(smem);
    const int tid  = threadIdx.x;
    const int wid  = tid >> 5;
    const int lane = tid & 31;
    const int wm   = wid & 1;        // 2 warp-rows (64 each)
    const int wn   = wid >> 1;       // 8 warp-cols (32 each)

    // band-swizzled tile mapping (bands of 16 M-tiles)
    int bid = blockIdx.x;
    int bandCtas = 16 * Ntiles;
    int band = bid / bandCtas, rmd = bid % bandCtas;
    int nt = rmd >> 4;
    int mt = band * 16 + (rmd & 15);
    const size_t m0 = (size_t)mt * 128;
    const size_t n0 = (size_t)nt * 256;

    const size_t K2 = (size_t)K * 2;  // bytes per row
    const char* pAh = (const char*)(Ah + m0 * (size_t)K);
    const char* pAl = (const char*)(Al + m0 * (size_t)K);
    const char* pBh = (const char*)(Bh + n0 * (size_t)K);
    const char* pBl = (const char*)(Bl + n0 * (size_t)K);

    const int nk = K >> 5;   // BK = 32

    // loader coords (512 threads): A 512 chunks (1/thread), B 1024 (2/thread)
    const int cr = tid >> 2;          // row 0..127
    const int cc = tid & 3;           // 16B chunk in row

    const uint32_t aoffA = swoff(cr, cc);
    const uint32_t boff0 = swoff(cr, cc);
    const uint32_t boff1 = swoff(cr + 128, cc);

    // prologue: stages 0..2
#pragma unroll
    for (int s = 0; s < 3; ++s) {
        const uint32_t base = sb + s * STAGEB;
        const size_t kb = (size_t)s * 64;
        {
            size_t g = (size_t)cr * K2 + kb + (size_t)cc * 16;
            cpa16(base + aoffA,        pAh + g);
            cpa16(base + ASEC + aoffA, pAl + g);
        }
        {
            size_t g0 = (size_t)cr * K2 + kb + (size_t)cc * 16;
            size_t g1 = (size_t)(cr + 128) * K2 + kb + (size_t)cc * 16;
            cpa16(base + 2 * ASEC + boff0,        pBh + g0);
            cpa16(base + 2 * ASEC + BSEC + boff0, pBl + g0);
            cpa16(base + 2 * ASEC + boff1,        pBh + g1);
            cpa16(base + 2 * ASEC + BSEC + boff1, pBl + g1);
        }
        asm volatile("cp.async.commit_group;" ::: "memory");
    }

    float acc[4][4][4];
#pragma unroll
    for (int i = 0; i < 4; ++i)
#pragma unroll
        for (int j = 0; j < 4; ++j)
#pragma unroll
            for (int q = 0; q < 4; ++q) acc[i][j][q] = 0.0f;

    // ldmatrix per-lane row/column selectors (swizzle-aware)
    const int rl_a   = (lane & 7) + ((lane >> 3) & 1) * 8;
    const int sel_a  = (rl_a >> 1) & 3;
    const int cb_a   = lane >> 4;                       // 0/1
    const uint32_t arow = (uint32_t)(rl_a * 64);
    const uint32_t acol0 = (uint32_t)(((0 + cb_a) ^ sel_a) << 4);   // kk=0
    const uint32_t acol1 = (uint32_t)(((2 + cb_a) ^ sel_a) << 4);   // kk=1

    const int rl_b   = (lane & 7) + (lane >> 4) * 8;
    const int sel_b  = (rl_b >> 1) & 3;
    const int cb_b   = (lane >> 3) & 1;
    const uint32_t brow = (uint32_t)(rl_b * 64);
    const uint32_t bcol0 = (uint32_t)(((0 + cb_b) ^ sel_b) << 4);
    const uint32_t bcol1 = (uint32_t)(((2 + cb_b) ^ sel_b) << 4);

    for (int kt = 0; kt < nk; ++kt) {
        asm volatile("cp.async.wait_group 2;" ::: "memory");
        __syncthreads();

        const uint32_t sbase = sb + (kt & 3) * STAGEB;
        const uint32_t aH = sbase;
        const uint32_t aL = sbase + ASEC;
        const uint32_t bH = sbase + 2 * ASEC;
        const uint32_t bL = sbase + 2 * ASEC + BSEC;

#pragma unroll
        for (int kk = 0; kk < 2; ++kk) {
            const uint32_t acol = kk ? acol1 : acol0;
            const uint32_t bcol = kk ? bcol1 : bcol0;
            uint32_t ah[4][4], al[4][4], bh[4][2], bl[4][2];
#pragma unroll
            for (int mi = 0; mi < 4; ++mi) {
                uint32_t ra = (uint32_t)((wm * 64 + mi * 16) * 64) + arow + acol;
                ldsm4(ah[mi][0], ah[mi][1], ah[mi][2], ah[mi][3], aH + ra);
                ldsm4(al[mi][0], al[mi][1], al[mi][2], al[mi][3], aL + ra);
            }
#pragma unroll
            for (int nj = 0; nj < 2; ++nj) {
                uint32_t rb = (uint32_t)((wn * 32 + nj * 16) * 64) + brow + bcol;
                uint32_t t0, t1, t2, t3;
                ldsm4(t0, t1, t2, t3, bH + rb);
                bh[nj * 2][0] = t0; bh[nj * 2][1] = t1;
                bh[nj * 2 + 1][0] = t2; bh[nj * 2 + 1][1] = t3;
                ldsm4(t0, t1, t2, t3, bL + rb);
                bl[nj * 2][0] = t0; bl[nj * 2][1] = t1;
                bl[nj * 2 + 1][0] = t2; bl[nj * 2 + 1][1] = t3;
            }
#pragma unroll
            for (int mi = 0; mi < 4; ++mi)
#pragma unroll
                for (int ni = 0; ni < 4; ++ni) {
                    float* c = acc[mi][ni];
                    mma_bf16(c, ah[mi], bh[ni]);
                    mma_bf16(c, ah[mi], bl[ni]);
                    mma_bf16(c, al[mi], bh[ni]);
                }
        }

        // prefetch stage kt+3 (always commit one group)
        if (kt + 3 < nk) {
            const uint32_t base = sb + ((kt + 3) & 3) * STAGEB;
            const size_t kb = (size_t)(kt + 3) * 64;
            {
                size_t g = (size_t)cr * K2 + kb + (size_t)cc * 16;
                cpa16(base + aoffA,        pAh + g);
                cpa16(base + ASEC + aoffA, pAl + g);
            }
            {
                size_t g0 = (size_t)cr * K2 + kb + (size_t)cc * 16;
                size_t g1 = (size_t)(cr + 128) * K2 + kb + (size_t)cc * 16;
                cpa16(base + 2 * ASEC + boff0,        pBh + g0);
                cpa16(base + 2 * ASEC + BSEC + boff0, pBl + g0);
                cpa16(base + 2 * ASEC + boff1,        pBh + g1);
                cpa16(base + 2 * ASEC + BSEC + boff1, pBl + g1);
            }
        }
        asm volatile("cp.async.commit_group;" ::: "memory");
    }

    // ---- epilogue (register accumulators -> global) ----
    const size_t mw = m0 + wm * 64;
    const size_t nw = n0 + wn * 32;
    const int tr = lane >> 2;
    const int tc = (lane & 3) * 2;

#pragma unroll
    for (int mi = 0; mi < 4; ++mi) {
#pragma unroll
        for (int nj = 0; nj < 4; ++nj) {
            const float* c = acc[mi][nj];
            const size_t row = mw + mi * 16 + tr;
            const size_t col = nw + nj * 8 + tc;
#pragma unroll
            for (int h = 0; h < 2; ++h) {
                const size_t rr = row + h * 8;
                const size_t base = rr * (size_t)N + col;
                float v0 = c[h * 2], v1 = c[h * 2 + 1];
                if (epi == 0) {
                    v0 = fmaxf(v0, 0.0f); v0 *= v0;
                    v1 = fmaxf(v1, 0.0f); v1 *= v1;
                    __nv_bfloat16 h0, l0, h1, l1;
                    split1(v0, h0, l0);
                    split1(v1, h1, l1);
                    *reinterpret_cast<uint32_t*>(Ch + base) = pbf2(h0, h1);
                    *reinterpret_cast<uint32_t*>(Cl + base) = pbf2(l0, l1);
                } else if (epi == 1) {
                    float2 o;
                    o.x = 1.0f / (1.0f + expf(-v0));
                    o.y = 1.0f / (1.0f + expf(-v1));
                    *reinterpret_cast<float2*>(Cf + base) = o;
                } else {
                    float2 rv = *reinterpret_cast<const float2*>(Rm + base);
                    float2 o;
                    o.x = v0 * rv.x;
                    o.y = v1 * rv.y;
                    *reinterpret_cast<float2*>(Cf + base) = o;
                }
            }
        }
    }
}

// ---------------- launch -----------------------------------------------------
extern "C" void kernel_launch(void* const* d_in, const int* in_sizes, int n_in,
                              void* d_out, int out_size) {
    const float* x  = (const float*)d_in[0];
    const float* ls = (const float*)d_in[1];
    const float* mk = (const float*)d_in[2];
    const float* mr = (const float*)d_in[3];
    const float* kw = (const float*)d_in[4];   // (F, C)
    const float* rw = (const float*)d_in[5];   // (C, C)
    const float* vw = (const float*)d_in[6];   // (C, F)
    float* out = (float*)d_out;

    __nv_bfloat16 *xkh, *xkl, *xrh, *xrl, *sh, *sl, *kwh, *kwl, *rwh, *rwl, *vwh, *vwl;
    float* r;
    cudaGetSymbolAddress((void**)&xkh, g_xkh);
    cudaGetSymbolAddress((void**)&xkl, g_xkl);
    cudaGetSymbolAddress((void**)&xrh, g_xrh);
    cudaGetSymbolAddress((void**)&xrl, g_xrl);
    cudaGetSymbolAddress((void**)&sh,  g_sh);
    cudaGetSymbolAddress((void**)&sl,  g_sl);
    cudaGetSymbolAddress((void**)&kwh, g_kwh);
    cudaGetSymbolAddress((void**)&kwl, g_kwl);
    cudaGetSymbolAddress((void**)&rwh, g_rwh);
    cudaGetSymbolAddress((void**)&rwl, g_rwl);
    cudaGetSymbolAddress((void**)&vwh, g_vwh);
    cudaGetSymbolAddress((void**)&vwl, g_vwl);
    cudaGetSymbolAddress((void**)&r,   g_r);

    cudaFuncSetAttribute(gemm_mma, cudaFuncAttributeMaxDynamicSharedMemorySize, SMEMSZ);

    // 1) token-shift mix + split
    mix_split_kernel<<<(MDIM * (CDIM / 4)) / 256, 256>>>(
        (const float4*)x, (const float4*)ls, (const float4*)mk, (const float4*)mr,
        (uint2*)xkh, (uint2*)xkl, (uint2*)xrh, (uint2*)xrl);

    // 2) weight splits
    {
        size_t n8;
        n8 = (size_t)FDIM * CDIM / 8;
        split_kernel<<<(unsigned)((n8 + 255) / 256), 256>>>((const float4*)kw, (uint4*)kwh, (uint4*)kwl, n8);
        n8 = (size_t)CDIM * CDIM / 8;
        split_kernel<<<(unsigned)((n8 + 255) / 256), 256>>>((const float4*)rw, (uint4*)rwh, (uint4*)rwl, n8);
        n8 = (size_t)CDIM * FDIM / 8;
        split_kernel<<<(unsigned)((n8 + 255) / 256), 256>>>((const float4*)vw, (uint4*)vwh, (uint4*)vwl, n8);
    }

    // 3) S = relu(xk @ Kw^T)^2  -> split bf16       [M=8192, N=14336, K=4096]
    gemm_mma<<<(MDIM / 128) * (FDIM / 256), 512, SMEMSZ>>>(
        xkh, xkl, kwh, kwl, FDIM, CDIM, FDIM / 256, 0, nullptr, sh, sl, nullptr);

    // 4) R = sigmoid(xr @ Rw^T) -> fp32             [M=8192, N=4096, K=4096]
    gemm_mma<<<(MDIM / 128) * (CDIM / 256), 512, SMEMSZ>>>(
        xrh, xrl, rwh, rwl, CDIM, CDIM, CDIM / 256, 1, r, nullptr, nullptr, nullptr);

    // 5) out = R * (S @ Vw^T)   -> fp32             [M=8192, N=4096, K=14336]
    gemm_mma<<<(MDIM / 128) * (CDIM / 256), 512, SMEMSZ>>>(
        sh, sl, vwh, vwl, CDIM, FDIM, CDIM / 256, 2, out, nullptr, nullptr, r);

    // 6) new_state = x[:, -1, :]
    state_kernel<<<(BDIM * CDIM) / 256, 256>>>(x, out + (size_t)MDIM * CDIM);
}

// round 8
// speedup vs baseline: 2.9705x; 1.3149x over previous
#include <cuda_runtime.h>
#include <cuda_fp16.h>
#include <cstdint>
#include <math.h>

#define BDIM 4
#define TDIM 2048
#define CDIM 4096
#define FDIM 14336
#define MDIM (BDIM * TDIM)   // 8192

// ---------------- scratch (device globals; allocation-free rule) -----------
__device__ __half g_xk [(size_t)MDIM * CDIM];
__device__ __half g_xr [(size_t)MDIM * CDIM];
__device__ __half g_s  [(size_t)MDIM * FDIM];
__device__ __half g_kwh[(size_t)FDIM * CDIM];
__device__ __half g_kwl[(size_t)FDIM * CDIM];
__device__ __half g_rwh[(size_t)CDIM * CDIM];
__device__ __half g_rwl[(size_t)CDIM * CDIM];
__device__ __half g_vwh[(size_t)CDIM * FDIM];
__device__ __half g_vwl[(size_t)CDIM * FDIM];
__device__ float  g_r  [(size_t)MDIM * CDIM];

// ---------------- helpers ----------------------------------------------------
__device__ __forceinline__ uint32_t smem_u32(const void* p) {
    uint32_t a;
    asm("{ .reg .u64 t; cvta.to.shared.u64 t, %1; cvt.u32.u64 %0, t; }" : "=r"(a) : "l"(p));
    return a;
}
__device__ __forceinline__ void cpa16(uint32_t dst, const void* src) {
    asm volatile("cp.async.cg.shared.global [%0], [%1], 16;" :: "r"(dst), "l"(src));
}
__device__ __forceinline__ void ldsm4(uint32_t& r0, uint32_t& r1, uint32_t& r2, uint32_t& r3,
                                      uint32_t addr) {
    asm volatile("ldmatrix.sync.aligned.m8n8.x4.shared.b16 {%0,%1,%2,%3}, [%4];"
                 : "=r"(r0), "=r"(r1), "=r"(r2), "=r"(r3) : "r"(addr));
}
__device__ __forceinline__ void mma_f16(float* c, const uint32_t* a, const uint32_t* b) {
    asm volatile(
        "mma.sync.aligned.m16n8k16.row.col.f32.f16.f16.f32 "
        "{%0,%1,%2,%3}, {%4,%5,%6,%7}, {%8,%9}, {%0,%1,%2,%3};"
        : "+f"(c[0]), "+f"(c[1]), "+f"(c[2]), "+f"(c[3])
        : "r"(a[0]), "r"(a[1]), "r"(a[2]), "r"(a[3]), "r"(b[0]), "r"(b[1]));
}
__device__ __forceinline__ uint32_t ph2(__half a, __half b) {
    __half2 t = __halves2half2(a, b);
    return *reinterpret_cast<uint32_t*>(&t);
}
__device__ __forceinline__ void splith(float v, __half& h, __half& l) {
    h = __float2half_rn(v);
    l = __float2half_rn(v - __half2float(h));
}

// 64B-row XOR swizzle: 16B chunk c at row r stored at chunk (c ^ ((r>>1)&3))
__device__ __forceinline__ uint32_t swoff(int r, int c) {
    return (uint32_t)(r * 64 + ((c ^ ((r >> 1) & 3)) << 4));
}

// ---------------- elementwise kernels ---------------------------------------
__global__ void mix_kernel(const float4* __restrict__ x,
                           const float4* __restrict__ ls,
                           const float4* __restrict__ mk,
                           const float4* __restrict__ mr,
                           uint2* __restrict__ xk, uint2* __restrict__ xr) {
    const int C4 = CDIM / 4;
    int idx = blockIdx.x * blockDim.x + threadIdx.x;
    int c4 = idx % C4;
    int bt = idx / C4;
    int t  = bt % TDIM;
    int b  = bt / TDIM;

    float4 xv = x[idx];
    float4 pv = (t == 0) ? ls[b * C4 + c4] : x[idx - C4];
    float4 k4 = mk[c4];
    float4 r4 = mr[c4];

    float kk[4], rr[4];
    kk[0] = fmaf(pv.x - xv.x, k4.x, xv.x);
    kk[1] = fmaf(pv.y - xv.y, k4.y, xv.y);
    kk[2] = fmaf(pv.z - xv.z, k4.z, xv.z);
    kk[3] = fmaf(pv.w - xv.w, k4.w, xv.w);
    rr[0] = fmaf(pv.x - xv.x, r4.x, xv.x);
    rr[1] = fmaf(pv.y - xv.y, r4.y, xv.y);
    rr[2] = fmaf(pv.z - xv.z, r4.z, xv.z);
    rr[3] = fmaf(pv.w - xv.w, r4.w, xv.w);

    xk[idx] = make_uint2(ph2(__float2half_rn(kk[0]), __float2half_rn(kk[1])),
                         ph2(__float2half_rn(kk[2]), __float2half_rn(kk[3])));
    xr[idx] = make_uint2(ph2(__float2half_rn(rr[0]), __float2half_rn(rr[1])),
                         ph2(__float2half_rn(rr[2]), __float2half_rn(rr[3])));
}

__global__ void split_kernel(const float4* __restrict__ in,
                             uint4* __restrict__ oh, uint4* __restrict__ ol,
                             size_t n8) {
    size_t i = (size_t)blockIdx.x * blockDim.x + threadIdx.x;
    if (i >= n8) return;
    float4 a = in[2 * i], b = in[2 * i + 1];
    float v[8] = {a.x, a.y, a.z, a.w, b.x, b.y, b.z, b.w};
    uint32_t hw[4], lw[4];
#pragma unroll
    for (int j = 0; j < 4; ++j) {
        __half h0, l0, h1, l1;
        splith(v[2 * j], h0, l0);
        splith(v[2 * j + 1], h1, l1);
        hw[j] = ph2(h0, h1);
        lw[j] = ph2(l0, l1);
    }
    oh[i] = make_uint4(hw[0], hw[1], hw[2], hw[3]);
    ol[i] = make_uint4(lw[0], lw[1], lw[2], lw[3]);
}

__global__ void state_kernel(const float* __restrict__ x, float* __restrict__ outs) {
    int idx = blockIdx.x * blockDim.x + threadIdx.x;
    int b = idx / CDIM;
    int c = idx % CDIM;
    outs[idx] = x[((size_t)b * TDIM + (TDIM - 1)) * CDIM + c];
}

// ---------------- fp16 HMMA GEMM ----------------------------------------------
// C[M,N] = A[M,K] * (Bh+Bl)[N,K]^T : A single fp16, B 2-term fp16 split.
// 2 MMAs per k16. CTA 128x256, 16 warps (512 thr), warp 64x32, BK=32,
// 5-stage cp.async, XOR-swizzled 64B rows.
// stage: A(128x64B) | Bh(256x64B) | Bl(256x64B)
#define ASEC   (128 * 64)            // 8192
#define BSEC   (256 * 64)            // 16384
#define STAGEB (ASEC + 2 * BSEC)     // 40960
#define NSTAGE 5
#define SMEMSZ (NSTAGE * STAGEB)     // 204800

__global__ void __launch_bounds__(512, 1)
gemm_f16(const __half* __restrict__ A,
         const __half* __restrict__ Bh, const __half* __restrict__ Bl,
         int N, int K, int Ntiles, int epi,
         float* __restrict__ Cf, __half* __restrict__ Chf,
         const float* __restrict__ Rm) {
    extern __shared__ char smem[];
    const uint32_t sb = smem_u32(smem);
    const int tid  = threadIdx.x;
    const int wid  = tid >> 5;
    const int lane = tid & 31;
    const int wm   = wid & 1;        // 2 warp-rows (64 each)
    const int wn   = wid >> 1;       // 8 warp-cols (32 each)

    // band-swizzled tile mapping (bands of 16 M-tiles)
    int bid = blockIdx.x;
    int bandCtas = 16 * Ntiles;
    int band = bid / bandCtas, rmd = bid % bandCtas;
    int nt = rmd >> 4;
    int mt = band * 16 + (rmd & 15);
    const size_t m0 = (size_t)mt * 128;
    const size_t n0 = (size_t)nt * 256;

    const size_t K2 = (size_t)K * 2;  // bytes per row
    const char* pA  = (const char*)(A  + m0 * (size_t)K);
    const char* pBh = (const char*)(Bh + n0 * (size_t)K);
    const char* pBl = (const char*)(Bl + n0 * (size_t)K);

    const int nk = K >> 5;   // BK = 32 halfs = 64B

    // loader coords (512 thr): A 512 chunks (1/thread), B 2x1024 (4/thread)
    const int cr = tid >> 2;          // row 0..127
    const int cc = tid & 3;           // 16B chunk in row

    const uint32_t aoff  = swoff(cr, cc);
    const uint32_t boff0 = swoff(cr, cc);
    const uint32_t boff1 = swoff(cr + 128, cc);

    // prologue: stages 0..3
#pragma unroll
    for (int s = 0; s < 4; ++s) {
        const uint32_t base = sb + s * STAGEB;
        const size_t kb = (size_t)s * 64;
        {
            size_t g = (size_t)cr * K2 + kb + (size_t)cc * 16;
            cpa16(base + aoff, pA + g);
        }
        {
            size_t g0 = (size_t)cr * K2 + kb + (size_t)cc * 16;
            size_t g1 = (size_t)(cr + 128) * K2 + kb + (size_t)cc * 16;
            cpa16(base + ASEC + boff0,        pBh + g0);
            cpa16(base + ASEC + boff1,        pBh + g1);
            cpa16(base + ASEC + BSEC + boff0, pBl + g0);
            cpa16(base + ASEC + BSEC + boff1, pBl + g1);
        }
        asm volatile("cp.async.commit_group;" ::: "memory");
    }

    float acc[4][4][4];
#pragma unroll
    for (int i = 0; i < 4; ++i)
#pragma unroll
        for (int j = 0; j < 4; ++j)
#pragma unroll
            for (int q = 0; q < 4; ++q) acc[i][j][q] = 0.0f;

    // ldmatrix per-lane selectors (swizzle-aware), same derivation as R7
    const int rl_a   = (lane & 7) + ((lane >> 3) & 1) * 8;
    const int sel_a  = (rl_a >> 1) & 3;
    const int cb_a   = lane >> 4;
    const uint32_t arow  = (uint32_t)(rl_a * 64);
    const uint32_t acol0 = (uint32_t)(((0 + cb_a) ^ sel_a) << 4);
    const uint32_t acol1 = (uint32_t)(((2 + cb_a) ^ sel_a) << 4);

    const int rl_b   = (lane & 7) + (lane >> 4) * 8;
    const int sel_b  = (rl_b >> 1) & 3;
    const int cb_b   = (lane >> 3) & 1;
    const uint32_t brow  = (uint32_t)(rl_b * 64);
    const uint32_t bcol0 = (uint32_t)(((0 + cb_b) ^ sel_b) << 4);
    const uint32_t bcol1 = (uint32_t)(((2 + cb_b) ^ sel_b) << 4);

    int stC = 0;               // compute stage (kt % 5)
    int stP = 4;               // prefetch stage ((kt+4) % 5)
    for (int kt = 0; kt < nk; ++kt) {
        asm volatile("cp.async.wait_group 3;" ::: "memory");
        __syncthreads();

        // prefetch kt+4 into the stage freed last iteration
        if (kt + 4 < nk) {
            const uint32_t base = sb + stP * STAGEB;
            const size_t kb = (size_t)(kt + 4) * 64;
            {
                size_t g = (size_t)cr * K2 + kb + (size_t)cc * 16;
                cpa16(base + aoff, pA + g);
            }
            {
                size_t g0 = (size_t)cr * K2 + kb + (size_t)cc * 16;
                size_t g1 = (size_t)(cr + 128) * K2 + kb + (size_t)cc * 16;
                cpa16(base + ASEC + boff0,        pBh + g0);
                cpa16(base + ASEC + boff1,        pBh + g1);
                cpa16(base + ASEC + BSEC + boff0, pBl + g0);
                cpa16(base + ASEC + BSEC + boff1, pBl + g1);
            }
        }
        asm volatile("cp.async.commit_group;" ::: "memory");

        const uint32_t sbase = sb + stC * STAGEB;
        const uint32_t aS = sbase;
        const uint32_t bHs = sbase + ASEC;
        const uint32_t bLs = sbase + ASEC + BSEC;

#pragma unroll
        for (int kk = 0; kk < 2; ++kk) {
            const uint32_t acol = kk ? acol1 : acol0;
            const uint32_t bcol = kk ? bcol1 : bcol0;
            uint32_t af[4][4], bh[4][2], bl[4][2];
#pragma unroll
            for (int mi = 0; mi < 4; ++mi) {
                uint32_t ra = (uint32_t)((wm * 64 + mi * 16) * 64) + arow + acol;
                ldsm4(af[mi][0], af[mi][1], af[mi][2], af[mi][3], aS + ra);
            }
#pragma unroll
            for (int nj = 0; nj < 2; ++nj) {
                uint32_t rb = (uint32_t)((wn * 32 + nj * 16) * 64) + brow + bcol;
                uint32_t t0, t1, t2, t3;
                ldsm4(t0, t1, t2, t3, bHs + rb);
                bh[nj * 2][0] = t0; bh[nj * 2][1] = t1;
                bh[nj * 2 + 1][0] = t2; bh[nj * 2 + 1][1] = t3;
                ldsm4(t0, t1, t2, t3, bLs + rb);
                bl[nj * 2][0] = t0; bl[nj * 2][1] = t1;
                bl[nj * 2 + 1][0] = t2; bl[nj * 2 + 1][1] = t3;
            }
#pragma unroll
            for (int mi = 0; mi < 4; ++mi)
#pragma unroll
                for (int ni = 0; ni < 4; ++ni) {
                    float* c = acc[mi][ni];
                    mma_f16(c, af[mi], bh[ni]);
                    mma_f16(c, af[mi], bl[ni]);
                }
        }

        if (++stC == NSTAGE) stC = 0;
        if (++stP == NSTAGE) stP = 0;
    }

    // ---- epilogue ----
    const size_t mw = m0 + wm * 64;
    const size_t nw = n0 + wn * 32;
    const int tr = lane >> 2;
    const int tc = (lane & 3) * 2;

#pragma unroll
    for (int mi = 0; mi < 4; ++mi) {
#pragma unroll
        for (int nj = 0; nj < 4; ++nj) {
            const float* c = acc[mi][nj];
            const size_t row = mw + mi * 16 + tr;
            const size_t col = nw + nj * 8 + tc;
#pragma unroll
            for (int h = 0; h < 2; ++h) {
                const size_t rr = row + h * 8;
                const size_t base = rr * (size_t)N + col;
                float v0 = c[h * 2], v1 = c[h * 2 + 1];
                if (epi == 0) {                 // relu^2 -> single fp16
                    v0 = fmaxf(v0, 0.0f); v0 *= v0;
                    v1 = fmaxf(v1, 0.0f); v1 *= v1;
                    *reinterpret_cast<uint32_t*>(Chf + base) =
                        ph2(__float2half_rn(v0), __float2half_rn(v1));
                } else if (epi == 1) {          // sigmoid -> fp32
                    float2 o;
                    o.x = 1.0f / (1.0f + expf(-v0));
                    o.y = 1.0f / (1.0f + expf(-v1));
                    *reinterpret_cast<float2*>(Cf + base) = o;
                } else {                        // * r -> fp32
                    float2 rv = *reinterpret_cast<const float2*>(Rm + base);
                    float2 o;
                    o.x = v0 * rv.x;
                    o.y = v1 * rv.y;
                    *reinterpret_cast<float2*>(Cf + base) = o;
                }
            }
        }
    }
}

// ---------------- launch -----------------------------------------------------
extern "C" void kernel_launch(void* const* d_in, const int* in_sizes, int n_in,
                              void* d_out, int out_size) {
    const float* x  = (const float*)d_in[0];
    const float* ls = (const float*)d_in[1];
    const float* mk = (const float*)d_in[2];
    const float* mr = (const float*)d_in[3];
    const float* kw = (const float*)d_in[4];   // (F, C)
    const float* rw = (const float*)d_in[5];   // (C, C)
    const float* vw = (const float*)d_in[6];   // (C, F)
    float* out = (float*)d_out;

    __half *xk, *xr, *s, *kwh, *kwl, *rwh, *rwl, *vwh, *vwl;
    float* r;
    cudaGetSymbolAddress((void**)&xk,  g_xk);
    cudaGetSymbolAddress((void**)&xr,  g_xr);
    cudaGetSymbolAddress((void**)&s,   g_s);
    cudaGetSymbolAddress((void**)&kwh, g_kwh);
    cudaGetSymbolAddress((void**)&kwl, g_kwl);
    cudaGetSymbolAddress((void**)&rwh, g_rwh);
    cudaGetSymbolAddress((void**)&rwl, g_rwl);
    cudaGetSymbolAddress((void**)&vwh, g_vwh);
    cudaGetSymbolAddress((void**)&vwl, g_vwl);
    cudaGetSymbolAddress((void**)&r,   g_r);

    cudaFuncSetAttribute(gemm_f16, cudaFuncAttributeMaxDynamicSharedMemorySize, SMEMSZ);

    // 1) token-shift mix -> fp16 xk, xr
    mix_kernel<<<(MDIM * (CDIM / 4)) / 256, 256>>>(
        (const float4*)x, (const float4*)ls, (const float4*)mk, (const float4*)mr,
        (uint2*)xk, (uint2*)xr);

    // 2) weight splits (fp16 h+l)
    {
        size_t n8;
        n8 = (size_t)FDIM * CDIM / 8;
        split_kernel<<<(unsigned)((n8 + 255) / 256), 256>>>((const float4*)kw, (uint4*)kwh, (uint4*)kwl, n8);
        n8 = (size_t)CDIM * CDIM / 8;
        split_kernel<<<(unsigned)((n8 + 255) / 256), 256>>>((const float4*)rw, (uint4*)rwh, (uint4*)rwl, n8);
        n8 = (size_t)CDIM * FDIM / 8;
        split_kernel<<<(unsigned)((n8 + 255) / 256), 256>>>((const float4*)vw, (uint4*)vwh, (uint4*)vwl, n8);
    }

    // 3) S = relu(xk @ Kw^T)^2 -> fp16           [M=8192, N=14336, K=4096]
    gemm_f16<<<(MDIM / 128) * (FDIM / 256), 512, SMEMSZ>>>(
        xk, kwh, kwl, FDIM, CDIM, FDIM / 256, 0, nullptr, s, nullptr);

    // 4) R = sigmoid(xr @ Rw^T) -> fp32          [M=8192, N=4096, K=4096]
    gemm_f16<<<(MDIM / 128) * (CDIM / 256), 512, SMEMSZ>>>(
        xr, rwh, rwl, CDIM, CDIM, CDIM / 256, 1, r, nullptr, nullptr);

    // 5) out = R * (S @ Vw^T)  -> fp32           [M=8192, N=4096, K=14336]
    gemm_f16<<<(MDIM / 128) * (CDIM / 256), 512, SMEMSZ>>>(
        s, vwh, vwl, CDIM, FDIM, CDIM / 256, 2, out, nullptr, r);

    // 6) new_state = x[:, -1, :]
    state_kernel<<<(BDIM * CDIM) / 256, 256>>>(x, out + (size_t)MDIM * CDIM);
}

// round 9
// speedup vs baseline: 3.9753x; 1.3383x over previous
#include <cuda_runtime.h>
#include <cuda_fp16.h>
#include <cstdint>
#include <math.h>

#define BDIM 4
#define TDIM 2048
#define CDIM 4096
#define FDIM 14336
#define MDIM (BDIM * TDIM)   // 8192

// ---------------- scratch (device globals; allocation-free rule) -----------
__device__ __half g_xk [(size_t)MDIM * CDIM];
__device__ __half g_xr [(size_t)MDIM * CDIM];
__device__ __half g_s  [(size_t)MDIM * FDIM];
__device__ __half g_kwh[(size_t)FDIM * CDIM];
__device__ __half g_kwl[(size_t)FDIM * CDIM];
__device__ __half g_rw [(size_t)CDIM * CDIM];
__device__ __half g_vw [(size_t)CDIM * FDIM];
__device__ float  g_r  [(size_t)MDIM * CDIM];

// ---------------- helpers ----------------------------------------------------
__device__ __forceinline__ uint32_t smem_u32(const void* p) {
    uint32_t a;
    asm("{ .reg .u64 t; cvta.to.shared.u64 t, %1; cvt.u32.u64 %0, t; }" : "=r"(a) : "l"(p));
    return a;
}
__device__ __forceinline__ void cpa16(uint32_t dst, const void* src) {
    asm volatile("cp.async.cg.shared.global [%0], [%1], 16;" :: "r"(dst), "l"(src));
}
__device__ __forceinline__ void ldsm4(uint32_t& r0, uint32_t& r1, uint32_t& r2, uint32_t& r3,
                                      uint32_t addr) {
    asm volatile("ldmatrix.sync.aligned.m8n8.x4.shared.b16 {%0,%1,%2,%3}, [%4];"
                 : "=r"(r0), "=r"(r1), "=r"(r2), "=r"(r3) : "r"(addr));
}
__device__ __forceinline__ void mma_f16(float* c, const uint32_t* a, const uint32_t* b) {
    asm volatile(
        "mma.sync.aligned.m16n8k16.row.col.f32.f16.f16.f32 "
        "{%0,%1,%2,%3}, {%4,%5,%6,%7}, {%8,%9}, {%0,%1,%2,%3};"
        : "+f"(c[0]), "+f"(c[1]), "+f"(c[2]), "+f"(c[3])
        : "r"(a[0]), "r"(a[1]), "r"(a[2]), "r"(a[3]), "r"(b[0]), "r"(b[1]));
}
__device__ __forceinline__ uint32_t ph2(__half a, __half b) {
    __half2 t = __halves2half2(a, b);
    return *reinterpret_cast<uint32_t*>(&t);
}
__device__ __forceinline__ void splith(float v, __half& h, __half& l) {
    h = __float2half_rn(v);
    l = __float2half_rn(v - __half2float(h));
}

// 64B-row XOR swizzle: 16B chunk c at row r stored at chunk (c ^ ((r>>1)&3))
__device__ __forceinline__ uint32_t swoff(int r, int c) {
    return (uint32_t)(r * 64 + ((c ^ ((r >> 1) & 3)) << 4));
}

// ---------------- elementwise kernels ---------------------------------------
__global__ void mix_kernel(const float4* __restrict__ x,
                           const float4* __restrict__ ls,
                           const float4* __restrict__ mk,
                           const float4* __restrict__ mr,
                           uint2* __restrict__ xk, uint2* __restrict__ xr) {
    const int C4 = CDIM / 4;
    int idx = blockIdx.x * blockDim.x + threadIdx.x;
    int c4 = idx % C4;
    int bt = idx / C4;
    int t  = bt % TDIM;
    int b  = bt / TDIM;

    float4 xv = x[idx];
    float4 pv = (t == 0) ? ls[b * C4 + c4] : x[idx - C4];
    float4 k4 = mk[c4];
    float4 r4 = mr[c4];

    float kk[4], rr[4];
    kk[0] = fmaf(pv.x - xv.x, k4.x, xv.x);
    kk[1] = fmaf(pv.y - xv.y, k4.y, xv.y);
    kk[2] = fmaf(pv.z - xv.z, k4.z, xv.z);
    kk[3] = fmaf(pv.w - xv.w, k4.w, xv.w);
    rr[0] = fmaf(pv.x - xv.x, r4.x, xv.x);
    rr[1] = fmaf(pv.y - xv.y, r4.y, xv.y);
    rr[2] = fmaf(pv.z - xv.z, r4.z, xv.z);
    rr[3] = fmaf(pv.w - xv.w, r4.w, xv.w);

    xk[idx] = make_uint2(ph2(__float2half_rn(kk[0]), __float2half_rn(kk[1])),
                         ph2(__float2half_rn(kk[2]), __float2half_rn(kk[3])));
    xr[idx] = make_uint2(ph2(__float2half_rn(rr[0]), __float2half_rn(rr[1])),
                         ph2(__float2half_rn(rr[2]), __float2half_rn(rr[3])));
}

__global__ void split_kernel(const float4* __restrict__ in,
                             uint4* __restrict__ oh, uint4* __restrict__ ol,
                             size_t n8) {
    size_t i = (size_t)blockIdx.x * blockDim.x + threadIdx.x;
    if (i >= n8) return;
    float4 a = in[2 * i], b = in[2 * i + 1];
    float v[8] = {a.x, a.y, a.z, a.w, b.x, b.y, b.z, b.w};
    uint32_t hw[4], lw[4];
#pragma unroll
    for (int j = 0; j < 4; ++j) {
        __half h0, l0, h1, l1;
        splith(v[2 * j], h0, l0);
        splith(v[2 * j + 1], h1, l1);
        hw[j] = ph2(h0, h1);
        lw[j] = ph2(l0, l1);
    }
    oh[i] = make_uint4(hw[0], hw[1], hw[2], hw[3]);
    ol[i] = make_uint4(lw[0], lw[1], lw[2], lw[3]);
}

__global__ void cvt_kernel(const float4* __restrict__ in,
                           uint4* __restrict__ oh, size_t n8) {
    size_t i = (size_t)blockIdx.x * blockDim.x + threadIdx.x;
    if (i >= n8) return;
    float4 a = in[2 * i], b = in[2 * i + 1];
    oh[i] = make_uint4(ph2(__float2half_rn(a.x), __float2half_rn(a.y)),
                       ph2(__float2half_rn(a.z), __float2half_rn(a.w)),
                       ph2(__float2half_rn(b.x), __float2half_rn(b.y)),
                       ph2(__float2half_rn(b.z), __float2half_rn(b.w)));
}

__global__ void state_kernel(const float* __restrict__ x, float* __restrict__ outs) {
    int idx = blockIdx.x * blockDim.x + threadIdx.x;
    int b = idx / CDIM;
    int c = idx % CDIM;
    outs[idx] = x[((size_t)b * TDIM + (TDIM - 1)) * CDIM + c];
}

// ---------------- fp16 HMMA GEMM, 2-term B (GEMM1) ----------------------------
// CTA 128x256, 16 warps, warp 64x32, BK=32, 5-stage, XOR-swizzled 64B rows.
#define ASEC   (128 * 64)            // 8192
#define BSEC   (256 * 64)            // 16384
#define STAGEB (ASEC + 2 * BSEC)     // 40960
#define NSTAGE 5
#define SMEMSZ (NSTAGE * STAGEB)     // 204800

__global__ void __launch_bounds__(512, 1)
gemm_f16_2t(const __half* __restrict__ A,
            const __half* __restrict__ Bh, const __half* __restrict__ Bl,
            int N, int K, int Ntiles,
            __half* __restrict__ Chf) {
    extern __shared__ char smem[];
    const uint32_t sb = smem_u32(smem);
    const int tid  = threadIdx.x;
    const int wid  = tid >> 5;
    const int lane = tid & 31;
    const int wm   = wid & 1;
    const int wn   = wid >> 1;

    int bid = blockIdx.x;
    int bandCtas = 16 * Ntiles;
    int band = bid / bandCtas, rmd = bid % bandCtas;
    int nt = rmd >> 4;
    int mt = band * 16 + (rmd & 15);
    const size_t m0 = (size_t)mt * 128;
    const size_t n0 = (size_t)nt * 256;

    const size_t K2 = (size_t)K * 2;
    const char* pA  = (const char*)(A  + m0 * (size_t)K);
    const char* pBh = (const char*)(Bh + n0 * (size_t)K);
    const char* pBl = (const char*)(Bl + n0 * (size_t)K);

    const int nk = K >> 5;

    const int cr = tid >> 2;
    const int cc = tid & 3;
    const uint32_t aoff  = swoff(cr, cc);
    const uint32_t boff0 = swoff(cr, cc);
    const uint32_t boff1 = swoff(cr + 128, cc);

#pragma unroll
    for (int s = 0; s < 4; ++s) {
        const uint32_t base = sb + s * STAGEB;
        const size_t kb = (size_t)s * 64;
        size_t g  = (size_t)cr * K2 + kb + (size_t)cc * 16;
        size_t g1 = (size_t)(cr + 128) * K2 + kb + (size_t)cc * 16;
        cpa16(base + aoff, pA + g);
        cpa16(base + ASEC + boff0,        pBh + g);
        cpa16(base + ASEC + boff1,        pBh + g1);
        cpa16(base + ASEC + BSEC + boff0, pBl + g);
        cpa16(base + ASEC + BSEC + boff1, pBl + g1);
        asm volatile("cp.async.commit_group;" ::: "memory");
    }

    float acc[4][4][4];
#pragma unroll
    for (int i = 0; i < 4; ++i)
#pragma unroll
        for (int j = 0; j < 4; ++j)
#pragma unroll
            for (int q = 0; q < 4; ++q) acc[i][j][q] = 0.0f;

    const int rl_a   = (lane & 7) + ((lane >> 3) & 1) * 8;
    const int sel_a  = (rl_a >> 1) & 3;
    const int cb_a   = lane >> 4;
    const uint32_t arow  = (uint32_t)(rl_a * 64);
    const uint32_t acol0 = (uint32_t)(((0 + cb_a) ^ sel_a) << 4);
    const uint32_t acol1 = (uint32_t)(((2 + cb_a) ^ sel_a) << 4);

    const int rl_b   = (lane & 7) + (lane >> 4) * 8;
    const int sel_b  = (rl_b >> 1) & 3;
    const int cb_b   = (lane >> 3) & 1;
    const uint32_t brow  = (uint32_t)(rl_b * 64);
    const uint32_t bcol0 = (uint32_t)(((0 + cb_b) ^ sel_b) << 4);
    const uint32_t bcol1 = (uint32_t)(((2 + cb_b) ^ sel_b) << 4);

    int stC = 0, stP = 4;
    for (int kt = 0; kt < nk; ++kt) {
        asm volatile("cp.async.wait_group 3;" ::: "memory");
        __syncthreads();

        if (kt + 4 < nk) {
            const uint32_t base = sb + stP * STAGEB;
            const size_t kb = (size_t)(kt + 4) * 64;
            size_t g  = (size_t)cr * K2 + kb + (size_t)cc * 16;
            size_t g1 = (size_t)(cr + 128) * K2 + kb + (size_t)cc * 16;
            cpa16(base + aoff, pA + g);
            cpa16(base + ASEC + boff0,        pBh + g);
            cpa16(base + ASEC + boff1,        pBh + g1);
            cpa16(base + ASEC + BSEC + boff0, pBl + g);
            cpa16(base + ASEC + BSEC + boff1, pBl + g1);
        }
        asm volatile("cp.async.commit_group;" ::: "memory");

        const uint32_t sbase = sb + stC * STAGEB;
        const uint32_t aS  = sbase;
        const uint32_t bHs = sbase + ASEC;
        const uint32_t bLs = sbase + ASEC + BSEC;

#pragma unroll
        for (int kk = 0; kk < 2; ++kk) {
            const uint32_t acol = kk ? acol1 : acol0;
            const uint32_t bcol = kk ? bcol1 : bcol0;
            uint32_t af[4][4], bh[4][2], bl[4][2];
#pragma unroll
            for (int mi = 0; mi < 4; ++mi) {
                uint32_t ra = (uint32_t)((wm * 64 + mi * 16) * 64) + arow + acol;
                ldsm4(af[mi][0], af[mi][1], af[mi][2], af[mi][3], aS + ra);
            }
#pragma unroll
            for (int nj = 0; nj < 2; ++nj) {
                uint32_t rb = (uint32_t)((wn * 32 + nj * 16) * 64) + brow + bcol;
                uint32_t t0, t1, t2, t3;
                ldsm4(t0, t1, t2, t3, bHs + rb);
                bh[nj * 2][0] = t0; bh[nj * 2][1] = t1;
                bh[nj * 2 + 1][0] = t2; bh[nj * 2 + 1][1] = t3;
                ldsm4(t0, t1, t2, t3, bLs + rb);
                bl[nj * 2][0] = t0; bl[nj * 2][1] = t1;
                bl[nj * 2 + 1][0] = t2; bl[nj * 2 + 1][1] = t3;
            }
#pragma unroll
            for (int mi = 0; mi < 4; ++mi)
#pragma unroll
                for (int ni = 0; ni < 4; ++ni) {
                    float* c = acc[mi][ni];
                    mma_f16(c, af[mi], bh[ni]);
                    mma_f16(c, af[mi], bl[ni]);
                }
        }

        if (++stC == NSTAGE) stC = 0;
        if (++stP == NSTAGE) stP = 0;
    }

    // epilogue: relu^2 -> fp16
    const size_t mw = m0 + wm * 64;
    const size_t nw = n0 + wn * 32;
    const int tr = lane >> 2;
    const int tc = (lane & 3) * 2;
#pragma unroll
    for (int mi = 0; mi < 4; ++mi)
#pragma unroll
        for (int nj = 0; nj < 4; ++nj) {
            const float* c = acc[mi][nj];
            const size_t row = mw + mi * 16 + tr;
            const size_t col = nw + nj * 8 + tc;
#pragma unroll
            for (int h = 0; h < 2; ++h) {
                const size_t base = (row + h * 8) * (size_t)N + col;
                float v0 = fmaxf(c[h * 2], 0.0f);     v0 *= v0;
                float v1 = fmaxf(c[h * 2 + 1], 0.0f); v1 *= v1;
                *reinterpret_cast<uint32_t*>(Chf + base) =
                    ph2(__float2half_rn(v0), __float2half_rn(v1));
            }
        }
}

// ---------------- fp16 HMMA GEMM, 1-term B (GEMM2/GEMM3) ----------------------
// CTA 128x256, 16 warps, warp 64x32, BK=32, 6-stage.
#define STAGE1 (ASEC + BSEC)         // 24576
#define NST1   6
#define SMEM1  (NST1 * STAGE1)       // 147456

__global__ void __launch_bounds__(512, 1)
gemm_f16_1t(const __half* __restrict__ A, const __half* __restrict__ B,
            int N, int K, int Ntiles, int epi,
            float* __restrict__ Cf, const float* __restrict__ Rm) {
    extern __shared__ char smem[];
    const uint32_t sb = smem_u32(smem);
    const int tid  = threadIdx.x;
    const int wid  = tid >> 5;
    const int lane = tid & 31;
    const int wm   = wid & 1;
    const int wn   = wid >> 1;

    int bid = blockIdx.x;
    int bandCtas = 16 * Ntiles;
    int band = bid / bandCtas, rmd = bid % bandCtas;
    int nt = rmd >> 4;
    int mt = band * 16 + (rmd & 15);
    const size_t m0 = (size_t)mt * 128;
    const size_t n0 = (size_t)nt * 256;

    const size_t K2 = (size_t)K * 2;
    const char* pA = (const char*)(A + m0 * (size_t)K);
    const char* pB = (const char*)(B + n0 * (size_t)K);

    const int nk = K >> 5;

    const int cr = tid >> 2;
    const int cc = tid & 3;
    const uint32_t aoff  = swoff(cr, cc);
    const uint32_t boff0 = swoff(cr, cc);
    const uint32_t boff1 = swoff(cr + 128, cc);

#pragma unroll
    for (int s = 0; s < 5; ++s) {
        const uint32_t base = sb + s * STAGE1;
        const size_t kb = (size_t)s * 64;
        size_t g  = (size_t)cr * K2 + kb + (size_t)cc * 16;
        size_t g1 = (size_t)(cr + 128) * K2 + kb + (size_t)cc * 16;
        cpa16(base + aoff, pA + g);
        cpa16(base + ASEC + boff0, pB + g);
        cpa16(base + ASEC + boff1, pB + g1);
        asm volatile("cp.async.commit_group;" ::: "memory");
    }

    float acc[4][4][4];
#pragma unroll
    for (int i = 0; i < 4; ++i)
#pragma unroll
        for (int j = 0; j < 4; ++j)
#pragma unroll
            for (int q = 0; q < 4; ++q) acc[i][j][q] = 0.0f;

    const int rl_a   = (lane & 7) + ((lane >> 3) & 1) * 8;
    const int sel_a  = (rl_a >> 1) & 3;
    const int cb_a   = lane >> 4;
    const uint32_t arow  = (uint32_t)(rl_a * 64);
    const uint32_t acol0 = (uint32_t)(((0 + cb_a) ^ sel_a) << 4);
    const uint32_t acol1 = (uint32_t)(((2 + cb_a) ^ sel_a) << 4);

    const int rl_b   = (lane & 7) + (lane >> 4) * 8;
    const int sel_b  = (rl_b >> 1) & 3;
    const int cb_b   = (lane >> 3) & 1;
    const uint32_t brow  = (uint32_t)(rl_b * 64);
    const uint32_t bcol0 = (uint32_t)(((0 + cb_b) ^ sel_b) << 4);
    const uint32_t bcol1 = (uint32_t)(((2 + cb_b) ^ sel_b) << 4);

    int stC = 0, stP = 5;
    for (int kt = 0; kt < nk; ++kt) {
        asm volatile("cp.async.wait_group 4;" ::: "memory");
        __syncthreads();

        if (kt + 5 < nk) {
            const uint32_t base = sb + stP * STAGE1;
            const size_t kb = (size_t)(kt + 5) * 64;
            size_t g  = (size_t)cr * K2 + kb + (size_t)cc * 16;
            size_t g1 = (size_t)(cr + 128) * K2 + kb + (size_t)cc * 16;
            cpa16(base + aoff, pA + g);
            cpa16(base + ASEC + boff0, pB + g);
            cpa16(base + ASEC + boff1, pB + g1);
        }
        asm volatile("cp.async.commit_group;" ::: "memory");

        const uint32_t sbase = sb + stC * STAGE1;
        const uint32_t aS = sbase;
        const uint32_t bS = sbase + ASEC;

#pragma unroll
        for (int kk = 0; kk < 2; ++kk) {
            const uint32_t acol = kk ? acol1 : acol0;
            const uint32_t bcol = kk ? bcol1 : bcol0;
            uint32_t af[4][4], bf[4][2];
#pragma unroll
            for (int mi = 0; mi < 4; ++mi) {
                uint32_t ra = (uint32_t)((wm * 64 + mi * 16) * 64) + arow + acol;
                ldsm4(af[mi][0], af[mi][1], af[mi][2], af[mi][3], aS + ra);
            }
#pragma unroll
            for (int nj = 0; nj < 2; ++nj) {
                uint32_t rb = (uint32_t)((wn * 32 + nj * 16) * 64) + brow + bcol;
                uint32_t t0, t1, t2, t3;
                ldsm4(t0, t1, t2, t3, bS + rb);
                bf[nj * 2][0] = t0; bf[nj * 2][1] = t1;
                bf[nj * 2 + 1][0] = t2; bf[nj * 2 + 1][1] = t3;
            }
#pragma unroll
            for (int mi = 0; mi < 4; ++mi)
#pragma unroll
                for (int ni = 0; ni < 4; ++ni)
                    mma_f16(acc[mi][ni], af[mi], bf[ni]);
        }

        if (++stC == NST1) stC = 0;
        if (++stP == NST1) stP = 0;
    }

    // epilogue
    const size_t mw = m0 + wm * 64;
    const size_t nw = n0 + wn * 32;
    const int tr = lane >> 2;
    const int tc = (lane & 3) * 2;
#pragma unroll
    for (int mi = 0; mi < 4; ++mi)
#pragma unroll
        for (int nj = 0; nj < 4; ++nj) {
            const float* c = acc[mi][nj];
            const size_t row = mw + mi * 16 + tr;
            const size_t col = nw + nj * 8 + tc;
#pragma unroll
            for (int h = 0; h < 2; ++h) {
                const size_t base = (row + h * 8) * (size_t)N + col;
                float v0 = c[h * 2], v1 = c[h * 2 + 1];
                if (epi == 1) {                 // sigmoid -> fp32
                    float2 o;
                    o.x = 1.0f / (1.0f + expf(-v0));
                    o.y = 1.0f / (1.0f + expf(-v1));
                    *reinterpret_cast<float2*>(Cf + base) = o;
                } else {                        // * r -> fp32
                    float2 rv = *reinterpret_cast<const float2*>(Rm + base);
                    float2 o;
                    o.x = v0 * rv.x;
                    o.y = v1 * rv.y;
                    *reinterpret_cast<float2*>(Cf + base) = o;
                }
            }
        }
}

// ---------------- launch -----------------------------------------------------
extern "C" void kernel_launch(void* const* d_in, const int* in_sizes, int n_in,
                              void* d_out, int out_size) {
    const float* x  = (const float*)d_in[0];
    const float* ls = (const float*)d_in[1];
    const float* mk = (const float*)d_in[2];
    const float* mr = (const float*)d_in[3];
    const float* kw = (const float*)d_in[4];   // (F, C)
    const float* rw = (const float*)d_in[5];   // (C, C)
    const float* vw = (const float*)d_in[6];   // (C, F)
    float* out = (float*)d_out;

    __half *xk, *xr, *s, *kwh, *kwl, *rwp, *vwp;
    float* r;
    cudaGetSymbolAddress((void**)&xk,  g_xk);
    cudaGetSymbolAddress((void**)&xr,  g_xr);
    cudaGetSymbolAddress((void**)&s,   g_s);
    cudaGetSymbolAddress((void**)&kwh, g_kwh);
    cudaGetSymbolAddress((void**)&kwl, g_kwl);
    cudaGetSymbolAddress((void**)&rwp, g_rw);
    cudaGetSymbolAddress((void**)&vwp, g_vw);
    cudaGetSymbolAddress((void**)&r,   g_r);

    cudaFuncSetAttribute(gemm_f16_2t, cudaFuncAttributeMaxDynamicSharedMemorySize, SMEMSZ);
    cudaFuncSetAttribute(gemm_f16_1t, cudaFuncAttributeMaxDynamicSharedMemorySize, SMEM1);

    // 1) token-shift mix -> fp16 xk, xr
    mix_kernel<<<(MDIM * (CDIM / 4)) / 256, 256>>>(
        (const float4*)x, (const float4*)ls, (const float4*)mk, (const float4*)mr,
        (uint2*)xk, (uint2*)xr);

    // 2) weight prep: kw split (2-term), rw/vw single fp16
    {
        size_t n8;
        n8 = (size_t)FDIM * CDIM / 8;
        split_kernel<<<(unsigned)((n8 + 255) / 256), 256>>>((const float4*)kw, (uint4*)kwh, (uint4*)kwl, n8);
        n8 = (size_t)CDIM * CDIM / 8;
        cvt_kernel<<<(unsigned)((n8 + 255) / 256), 256>>>((const float4*)rw, (uint4*)rwp, n8);
        n8 = (size_t)CDIM * FDIM / 8;
        cvt_kernel<<<(unsigned)((n8 + 255) / 256), 256>>>((const float4*)vw, (uint4*)vwp, n8);
    }

    // 3) S = relu(xk @ Kw^T)^2 -> fp16           [M=8192, N=14336, K=4096]
    gemm_f16_2t<<<(MDIM / 128) * (FDIM / 256), 512, SMEMSZ>>>(
        xk, kwh, kwl, FDIM, CDIM, FDIM / 256, s);

    // 4) R = sigmoid(xr @ Rw^T) -> fp32          [M=8192, N=4096, K=4096]
    gemm_f16_1t<<<(MDIM / 128) * (CDIM / 256), 512, SMEM1>>>(
        xr, rwp, CDIM, CDIM, CDIM / 256, 1, r, nullptr);

    // 5) out = R * (S @ Vw^T)  -> fp32           [M=8192, N=4096, K=14336]
    gemm_f16_1t<<<(MDIM / 128) * (CDIM / 256), 512, SMEM1>>>(
        s, vwp, CDIM, FDIM, CDIM / 256, 2, out, r);

    // 6) new_state = x[:, -1, :]
    state_kernel<<<(BDIM * CDIM) / 256, 256>>>(x, out + (size_t)MDIM * CDIM);
}

// round 10
// speedup vs baseline: 5.4281x; 1.3655x over previous
#include <cuda_runtime.h>
#include <cuda_fp16.h>
#include <cstdint>
#include <math.h>

#define BDIM 4
#define TDIM 2048
#define CDIM 4096
#define FDIM 14336
#define MDIM (BDIM * TDIM)   // 8192

// ---------------- scratch (device globals; allocation-free rule) -----------
__device__ __half g_xk [(size_t)MDIM * CDIM];
__device__ __half g_xr [(size_t)MDIM * CDIM];
__device__ __half g_s  [(size_t)MDIM * FDIM];
__device__ __half g_kw [(size_t)FDIM * CDIM];
__device__ __half g_rw [(size_t)CDIM * CDIM];
__device__ __half g_vw [(size_t)CDIM * FDIM];
__device__ float  g_r  [(size_t)MDIM * CDIM];

// ---------------- helpers ----------------------------------------------------
__device__ __forceinline__ uint32_t smem_u32(const void* p) {
    uint32_t a;
    asm("{ .reg .u64 t; cvta.to.shared.u64 t, %1; cvt.u32.u64 %0, t; }" : "=r"(a) : "l"(p));
    return a;
}
__device__ __forceinline__ void cpa16(uint32_t dst, const void* src) {
    asm volatile("cp.async.cg.shared.global [%0], [%1], 16;" :: "r"(dst), "l"(src));
}
__device__ __forceinline__ void ldsm4(uint32_t& r0, uint32_t& r1, uint32_t& r2, uint32_t& r3,
                                      uint32_t addr) {
    asm volatile("ldmatrix.sync.aligned.m8n8.x4.shared.b16 {%0,%1,%2,%3}, [%4];"
                 : "=r"(r0), "=r"(r1), "=r"(r2), "=r"(r3) : "r"(addr));
}
__device__ __forceinline__ void mma_f16(float* c, const uint32_t* a, const uint32_t* b) {
    asm volatile(
        "mma.sync.aligned.m16n8k16.row.col.f32.f16.f16.f32 "
        "{%0,%1,%2,%3}, {%4,%5,%6,%7}, {%8,%9}, {%0,%1,%2,%3};"
        : "+f"(c[0]), "+f"(c[1]), "+f"(c[2]), "+f"(c[3])
        : "r"(a[0]), "r"(a[1]), "r"(a[2]), "r"(a[3]), "r"(b[0]), "r"(b[1]));
}
__device__ __forceinline__ uint32_t ph2(__half a, __half b) {
    __half2 t = __halves2half2(a, b);
    return *reinterpret_cast<uint32_t*>(&t);
}

// 64B-row XOR swizzle: 16B chunk c at row r stored at chunk (c ^ ((r>>1)&3))
__device__ __forceinline__ uint32_t swoff(int r, int c) {
    return (uint32_t)(r * 64 + ((c ^ ((r >> 1) & 3)) << 4));
}

// ---------------- elementwise kernels ---------------------------------------
__global__ void mix_kernel(const float4* __restrict__ x,
                           const float4* __restrict__ ls,
                           const float4* __restrict__ mk,
                           const float4* __restrict__ mr,
                           uint2* __restrict__ xk, uint2* __restrict__ xr) {
    const int C4 = CDIM / 4;
    int idx = blockIdx.x * blockDim.x + threadIdx.x;
    int c4 = idx % C4;
    int bt = idx / C4;
    int t  = bt % TDIM;
    int b  = bt / TDIM;

    float4 xv = x[idx];
    float4 pv = (t == 0) ? ls[b * C4 + c4] : x[idx - C4];
    float4 k4 = mk[c4];
    float4 r4 = mr[c4];

    float kk[4], rr[4];
    kk[0] = fmaf(pv.x - xv.x, k4.x, xv.x);
    kk[1] = fmaf(pv.y - xv.y, k4.y, xv.y);
    kk[2] = fmaf(pv.z - xv.z, k4.z, xv.z);
    kk[3] = fmaf(pv.w - xv.w, k4.w, xv.w);
    rr[0] = fmaf(pv.x - xv.x, r4.x, xv.x);
    rr[1] = fmaf(pv.y - xv.y, r4.y, xv.y);
    rr[2] = fmaf(pv.z - xv.z, r4.z, xv.z);
    rr[3] = fmaf(pv.w - xv.w, r4.w, xv.w);

    xk[idx] = make_uint2(ph2(__float2half_rn(kk[0]), __float2half_rn(kk[1])),
                         ph2(__float2half_rn(kk[2]), __float2half_rn(kk[3])));
    xr[idx] = make_uint2(ph2(__float2half_rn(rr[0]), __float2half_rn(rr[1])),
                         ph2(__float2half_rn(rr[2]), __float2half_rn(rr[3])));
}

__global__ void cvt_kernel(const float4* __restrict__ in,
                           uint4* __restrict__ oh, size_t n8) {
    size_t i = (size_t)blockIdx.x * blockDim.x + threadIdx.x;
    if (i >= n8) return;
    float4 a = in[2 * i], b = in[2 * i + 1];
    oh[i] = make_uint4(ph2(__float2half_rn(a.x), __float2half_rn(a.y)),
                       ph2(__float2half_rn(a.z), __float2half_rn(a.w)),
                       ph2(__float2half_rn(b.x), __float2half_rn(b.y)),
                       ph2(__float2half_rn(b.z), __float2half_rn(b.w)));
}

__global__ void state_kernel(const float* __restrict__ x, float* __restrict__ outs) {
    int idx = blockIdx.x * blockDim.x + threadIdx.x;
    int b = idx / CDIM;
    int c = idx % CDIM;
    outs[idx] = x[((size_t)b * TDIM + (TDIM - 1)) * CDIM + c];
}

// ---------------- fp16 HMMA GEMM (all three GEMMs) ---------------------------
// C[M,N] = A[M,K] * B[N,K]^T, fp16 inputs, fp32 accum.
// CTA 128x256, 16 warps (512 thr), warp 64x32, BK=32, 6-stage cp.async,
// XOR-swizzled 64B rows. epi 0: relu^2->fp16 | 1: sigmoid->fp32 | 2: *Rm->fp32
#define ASEC   (128 * 64)            // 8192
#define BSEC   (256 * 64)            // 16384
#define STAGE1 (ASEC + BSEC)         // 24576
#define NST1   6
#define SMEM1  (NST1 * STAGE1)       // 147456

__global__ void __launch_bounds__(512, 1)
gemm_f16(const __half* __restrict__ A, const __half* __restrict__ B,
         int N, int K, int Ntiles, int epi,
         float* __restrict__ Cf, __half* __restrict__ Chf,
         const float* __restrict__ Rm) {
    extern __shared__ char smem[];
    const uint32_t sb = smem_u32(smem);
    const int tid  = threadIdx.x;
    const int wid  = tid >> 5;
    const int lane = tid & 31;
    const int wm   = wid & 1;        // 2 warp-rows (64 each)
    const int wn   = wid >> 1;       // 8 warp-cols (32 each)

    // band-swizzled tile mapping (bands of 16 M-tiles)
    int bid = blockIdx.x;
    int bandCtas = 16 * Ntiles;
    int band = bid / bandCtas, rmd = bid % bandCtas;
    int nt = rmd >> 4;
    int mt = band * 16 + (rmd & 15);
    const size_t m0 = (size_t)mt * 128;
    const size_t n0 = (size_t)nt * 256;

    const size_t K2 = (size_t)K * 2;
    const char* pA = (const char*)(A + m0 * (size_t)K);
    const char* pB = (const char*)(B + n0 * (size_t)K);

    const int nk = K >> 5;   // BK = 32

    const int cr = tid >> 2;
    const int cc = tid & 3;
    const uint32_t aoff  = swoff(cr, cc);
    const uint32_t boff0 = swoff(cr, cc);
    const uint32_t boff1 = swoff(cr + 128, cc);

#pragma unroll
    for (int s = 0; s < 5; ++s) {
        const uint32_t base = sb + s * STAGE1;
        const size_t kb = (size_t)s * 64;
        size_t g  = (size_t)cr * K2 + kb + (size_t)cc * 16;
        size_t g1 = (size_t)(cr + 128) * K2 + kb + (size_t)cc * 16;
        cpa16(base + aoff, pA + g);
        cpa16(base + ASEC + boff0, pB + g);
        cpa16(base + ASEC + boff1, pB + g1);
        asm volatile("cp.async.commit_group;" ::: "memory");
    }

    float acc[4][4][4];
#pragma unroll
    for (int i = 0; i < 4; ++i)
#pragma unroll
        for (int j = 0; j < 4; ++j)
#pragma unroll
            for (int q = 0; q < 4; ++q) acc[i][j][q] = 0.0f;

    const int rl_a   = (lane & 7) + ((lane >> 3) & 1) * 8;
    const int sel_a  = (rl_a >> 1) & 3;
    const int cb_a   = lane >> 4;
    const uint32_t arow  = (uint32_t)(rl_a * 64);
    const uint32_t acol0 = (uint32_t)(((0 + cb_a) ^ sel_a) << 4);
    const uint32_t acol1 = (uint32_t)(((2 + cb_a) ^ sel_a) << 4);

    const int rl_b   = (lane & 7) + (lane >> 4) * 8;
    const int sel_b  = (rl_b >> 1) & 3;
    const int cb_b   = (lane >> 3) & 1;
    const uint32_t brow  = (uint32_t)(rl_b * 64);
    const uint32_t bcol0 = (uint32_t)(((0 + cb_b) ^ sel_b) << 4);
    const uint32_t bcol1 = (uint32_t)(((2 + cb_b) ^ sel_b) << 4);

    int stC = 0, stP = 5;
    for (int kt = 0; kt < nk; ++kt) {
        asm volatile("cp.async.wait_group 4;" ::: "memory");
        __syncthreads();

        if (kt + 5 < nk) {
            const uint32_t base = sb + stP * STAGE1;
            const size_t kb = (size_t)(kt + 5) * 64;
            size_t g  = (size_t)cr * K2 + kb + (size_t)cc * 16;
            size_t g1 = (size_t)(cr + 128) * K2 + kb + (size_t)cc * 16;
            cpa16(base + aoff, pA + g);
            cpa16(base + ASEC + boff0, pB + g);
            cpa16(base + ASEC + boff1, pB + g1);
        }
        asm volatile("cp.async.commit_group;" ::: "memory");

        const uint32_t sbase = sb + stC * STAGE1;
        const uint32_t aS = sbase;
        const uint32_t bS = sbase + ASEC;

#pragma unroll
        for (int kk = 0; kk < 2; ++kk) {
            const uint32_t acol = kk ? acol1 : acol0;
            const uint32_t bcol = kk ? bcol1 : bcol0;
            uint32_t af[4][4], bf[4][2];
#pragma unroll
            for (int mi = 0; mi < 4; ++mi) {
                uint32_t ra = (uint32_t)((wm * 64 + mi * 16) * 64) + arow + acol;
                ldsm4(af[mi][0], af[mi][1], af[mi][2], af[mi][3], aS + ra);
            }
#pragma unroll
            for (int nj = 0; nj < 2; ++nj) {
                uint32_t rb = (uint32_t)((wn * 32 + nj * 16) * 64) + brow + bcol;
                uint32_t t0, t1, t2, t3;
                ldsm4(t0, t1, t2, t3, bS + rb);
                bf[nj * 2][0] = t0; bf[nj * 2][1] = t1;
                bf[nj * 2 + 1][0] = t2; bf[nj * 2 + 1][1] = t3;
            }
#pragma unroll
            for (int mi = 0; mi < 4; ++mi)
#pragma unroll
                for (int ni = 0; ni < 4; ++ni)
                    mma_f16(acc[mi][ni], af[mi], bf[ni]);
        }

        if (++stC == NST1) stC = 0;
        if (++stP == NST1) stP = 0;
    }

    // ---- epilogue ----
    const size_t mw = m0 + wm * 64;
    const size_t nw = n0 + wn * 32;
    const int tr = lane >> 2;
    const int tc = (lane & 3) * 2;
#pragma unroll
    for (int mi = 0; mi < 4; ++mi)
#pragma unroll
        for (int nj = 0; nj < 4; ++nj) {
            const float* c = acc[mi][nj];
            const size_t row = mw + mi * 16 + tr;
            const size_t col = nw + nj * 8 + tc;
#pragma unroll
            for (int h = 0; h < 2; ++h) {
                const size_t base = (row + h * 8) * (size_t)N + col;
                float v0 = c[h * 2], v1 = c[h * 2 + 1];
                if (epi == 0) {                 // relu^2 -> fp16
                    v0 = fmaxf(v0, 0.0f); v0 *= v0;
                    v1 = fmaxf(v1, 0.0f); v1 *= v1;
                    *reinterpret_cast<uint32_t*>(Chf + base) =
                        ph2(__float2half_rn(v0), __float2half_rn(v1));
                } else if (epi == 1) {          // sigmoid -> fp32
                    float2 o;
                    o.x = 1.0f / (1.0f + expf(-v0));
                    o.y = 1.0f / (1.0f + expf(-v1));
                    *reinterpret_cast<float2*>(Cf + base) = o;
                } else {                        // * r -> fp32
                    float2 rv = *reinterpret_cast<const float2*>(Rm + base);
                    float2 o;
                    o.x = v0 * rv.x;
                    o.y = v1 * rv.y;
                    *reinterpret_cast<float2*>(Cf + base) = o;
                }
            }
        }
}

// ---------------- launch -----------------------------------------------------
extern "C" void kernel_launch(void* const* d_in, const int* in_sizes, int n_in,
                              void* d_out, int out_size) {
    const float* x  = (const float*)d_in[0];
    const float* ls = (const float*)d_in[1];
    const float* mk = (const float*)d_in[2];
    const float* mr = (const float*)d_in[3];
    const float* kw = (const float*)d_in[4];   // (F, C)
    const float* rw = (const float*)d_in[5];   // (C, C)
    const float* vw = (const float*)d_in[6];   // (C, F)
    float* out = (float*)d_out;

    __half *xk, *xr, *s, *kwp, *rwp, *vwp;
    float* r;
    cudaGetSymbolAddress((void**)&xk,  g_xk);
    cudaGetSymbolAddress((void**)&xr,  g_xr);
    cudaGetSymbolAddress((void**)&s,   g_s);
    cudaGetSymbolAddress((void**)&kwp, g_kw);
    cudaGetSymbolAddress((void**)&rwp, g_rw);
    cudaGetSymbolAddress((void**)&vwp, g_vw);
    cudaGetSymbolAddress((void**)&r,   g_r);

    cudaFuncSetAttribute(gemm_f16, cudaFuncAttributeMaxDynamicSharedMemorySize, SMEM1);

    // 1) token-shift mix -> fp16 xk, xr
    mix_kernel<<<(MDIM * (CDIM / 4)) / 256, 256>>>(
        (const float4*)x, (const float4*)ls, (const float4*)mk, (const float4*)mr,
        (uint2*)xk, (uint2*)xr);

    // 2) weight prep: all single fp16
    {
        size_t n8;
        n8 = (size_t)FDIM * CDIM / 8;
        cvt_kernel<<<(unsigned)((n8 + 255) / 256), 256>>>((const float4*)kw, (uint4*)kwp, n8);
        n8 = (size_t)CDIM * CDIM / 8;
        cvt_kernel<<<(unsigned)((n8 + 255) / 256), 256>>>((const float4*)rw, (uint4*)rwp, n8);
        n8 = (size_t)CDIM * FDIM / 8;
        cvt_kernel<<<(unsigned)((n8 + 255) / 256), 256>>>((const float4*)vw, (uint4*)vwp, n8);
    }

    // 3) S = relu(xk @ Kw^T)^2 -> fp16           [M=8192, N=14336, K=4096]
    gemm_f16<<<(MDIM / 128) * (FDIM / 256), 512, SMEM1>>>(
        xk, kwp, FDIM, CDIM, FDIM / 256, 0, nullptr, s, nullptr);

    // 4) R = sigmoid(xr @ Rw^T) -> fp32          [M=8192, N=4096, K=4096]
    gemm_f16<<<(MDIM / 128) * (CDIM / 256), 512, SMEM1>>>(
        xr, rwp, CDIM, CDIM, CDIM / 256, 1, r, nullptr, nullptr);

    // 5) out = R * (S @ Vw^T)  -> fp32           [M=8192, N=4096, K=14336]
    gemm_f16<<<(MDIM / 128) * (CDIM / 256), 512, SMEM1>>>(
        s, vwp, CDIM, FDIM, CDIM / 256, 2, out, nullptr, r);

    // 6) new_state = x[:, -1, :]
    state_kernel<<<(BDIM * CDIM) / 256, 256>>>(x, out + (size_t)MDIM * CDIM);
}